// round 1
// baseline (speedup 1.0000x reference)
#include <cuda_runtime.h>
#include <math.h>

// ---------------------------------------------------------------------------
// Bert_Traj_Model: B=32, S=512, D=768, H=12, dh=64, FF=3072, L=12, fp32.
// Round 0: correct fp32 SIMT baseline. GEMMs: 128x128x8 tiled sgemm.
// Attention: flash-style 64x64 tiling with online softmax, exact masking.
// ---------------------------------------------------------------------------

namespace {
constexpr int kB  = 32;
constexpr int kS  = 512;
constexpr int kD  = 768;
constexpr int kH  = 12;
constexpr int kFF = 3072;
constexpr int kL  = 12;
constexpr int kM  = kB * kS;          // 16384 rows
}

// Scratch (device globals; allocation is forbidden).
__device__ float g_h [kM * kD];
__device__ float g_hn[kM * kD];
__device__ float g_q [kM * kD];
__device__ float g_k [kM * kD];
__device__ float g_v [kM * kD];
__device__ float g_o [kM * kD];
__device__ float g_ff[(size_t)kM * kFF];
__device__ float g_pe[kS * kD];

// ---------------------------------------------------------------------------
// Positional encoding (fp64 for exactness vs numpy-double reference).
// ---------------------------------------------------------------------------
__global__ void pe_kernel(float* __restrict__ pe) {
    int idx = blockIdx.x * blockDim.x + threadIdx.x;
    if (idx >= kS * kD) return;
    int s = idx / kD;
    int j = idx - s * kD;
    int i2 = j & ~1;
    double ang = (double)s * pow(10000.0, -(double)i2 / (double)kD);
    pe[idx] = (j & 1) ? (float)cos(ang) : (float)sin(ang);
}

// ---------------------------------------------------------------------------
// Embedding: tok_emb[x] + time_emb[time] + pe
// ---------------------------------------------------------------------------
__global__ void embed_kernel(const int* __restrict__ x, const int* __restrict__ tim,
                             const float* __restrict__ tok_emb,
                             const float* __restrict__ time_emb,
                             const float* __restrict__ pe,
                             float* __restrict__ out) {
    int idx = blockIdx.x * blockDim.x + threadIdx.x;
    if (idx >= kM * kD) return;
    int bs = idx / kD;
    int j  = idx - bs * kD;
    int s  = bs & (kS - 1);
    out[idx] = tok_emb[(size_t)x[bs] * kD + j] + time_emb[(size_t)tim[bs] * kD + j]
             + pe[s * kD + j];
}

// ---------------------------------------------------------------------------
// LayerNorm over last dim (768). One block (256 threads) per row.
// ---------------------------------------------------------------------------
__device__ __forceinline__ float block_reduce_sum(float v, float* sred) {
    #pragma unroll
    for (int o = 16; o > 0; o >>= 1) v += __shfl_xor_sync(0xffffffffu, v, o);
    int w = threadIdx.x >> 5;
    __syncthreads();                       // protect sred across calls
    if ((threadIdx.x & 31) == 0) sred[w] = v;
    __syncthreads();
    if (threadIdx.x == 0) {
        float t = sred[0];
        #pragma unroll
        for (int i = 1; i < 8; i++) t += sred[i];
        sred[0] = t;
    }
    __syncthreads();
    return sred[0];
}

__global__ void ln_kernel(const float* __restrict__ in, float* __restrict__ out,
                          const float* __restrict__ g, const float* __restrict__ b) {
    __shared__ float sred[8];
    int row = blockIdx.x;
    int tid = threadIdx.x;
    const float* ip = in + (size_t)row * kD;
    float v0 = ip[tid], v1 = ip[tid + 256], v2 = ip[tid + 512];
    float sum = block_reduce_sum(v0 + v1 + v2, sred);
    float mu = sum * (1.0f / 768.0f);
    float d0 = v0 - mu, d1 = v1 - mu, d2 = v2 - mu;
    float sq = block_reduce_sum(d0 * d0 + d1 * d1 + d2 * d2, sred);
    float inv = 1.0f / sqrtf(sq * (1.0f / 768.0f) + 1e-6f);
    float* op = out + (size_t)row * kD;
    op[tid]       = g[tid]       * d0 * inv + b[tid];
    op[tid + 256] = g[tid + 256] * d1 * inv + b[tid + 256];
    op[tid + 512] = g[tid + 512] * d2 * inv + b[tid + 512];
}

// ---------------------------------------------------------------------------
// SGEMM: C[M,N] = act(A[M,K] @ W[K,N] + bias[N]) (+ Res[M,N]).
// 128x128 tile, BK=8, 256 threads, 8x8 per thread. All dims divide exactly.
// ---------------------------------------------------------------------------
__global__ void sgemm_kernel(const float* __restrict__ A, const float* __restrict__ W,
                             const float* __restrict__ bias, const float* __restrict__ Res,
                             float* __restrict__ C, int M, int N, int K, int relu) {
    __shared__ __align__(16) float As[8 * 128];
    __shared__ __align__(16) float Bs[8 * 128];
    const int tid = threadIdx.x;
    const int tx = tid & 15, ty = tid >> 4;
    const int row0 = blockIdx.y * 128, col0 = blockIdx.x * 128;
    const int ar = tid >> 1, ac = (tid & 1) * 4;
    const int br = tid >> 5, bc = (tid & 31) * 4;

    float acc[8][8];
    #pragma unroll
    for (int i = 0; i < 8; i++)
        #pragma unroll
        for (int j = 0; j < 8; j++) acc[i][j] = 0.0f;

    const float* Ag = A + (size_t)(row0 + ar) * K + ac;
    const float* Bg = W + (size_t)br * N + col0 + bc;

    for (int k0 = 0; k0 < K; k0 += 8) {
        float4 a4 = *(const float4*)(Ag + k0);
        As[(ac + 0) * 128 + ar] = a4.x;
        As[(ac + 1) * 128 + ar] = a4.y;
        As[(ac + 2) * 128 + ar] = a4.z;
        As[(ac + 3) * 128 + ar] = a4.w;
        *(float4*)&Bs[br * 128 + bc] = *(const float4*)(Bg + (size_t)k0 * N);
        __syncthreads();
        #pragma unroll
        for (int kk = 0; kk < 8; kk++) {
            float ra[8], rb[8];
            *(float4*)&ra[0] = *(const float4*)&As[kk * 128 + ty * 8];
            *(float4*)&ra[4] = *(const float4*)&As[kk * 128 + ty * 8 + 4];
            *(float4*)&rb[0] = *(const float4*)&Bs[kk * 128 + tx * 8];
            *(float4*)&rb[4] = *(const float4*)&Bs[kk * 128 + tx * 8 + 4];
            #pragma unroll
            for (int i = 0; i < 8; i++)
                #pragma unroll
                for (int j = 0; j < 8; j++) acc[i][j] += ra[i] * rb[j];
        }
        __syncthreads();
    }

    #pragma unroll
    for (int i = 0; i < 8; i++) {
        size_t base = (size_t)(row0 + ty * 8 + i) * N + col0 + tx * 8;
        #pragma unroll
        for (int j0 = 0; j0 < 8; j0 += 4) {
            float4 bv = *(const float4*)(bias + col0 + tx * 8 + j0);
            float4 rv;
            rv.x = acc[i][j0 + 0] + bv.x;
            rv.y = acc[i][j0 + 1] + bv.y;
            rv.z = acc[i][j0 + 2] + bv.z;
            rv.w = acc[i][j0 + 3] + bv.w;
            if (relu) {
                rv.x = fmaxf(rv.x, 0.0f); rv.y = fmaxf(rv.y, 0.0f);
                rv.z = fmaxf(rv.z, 0.0f); rv.w = fmaxf(rv.w, 0.0f);
            }
            if (Res) {
                float4 rr = *(const float4*)(Res + base + j0);
                rv.x += rr.x; rv.y += rr.y; rv.z += rr.z; rv.w += rr.w;
            }
            *(float4*)(C + base + j0) = rv;
        }
    }
}

// ---------------------------------------------------------------------------
// Attention: one block per (q_tile=64, head, batch). Flash-style over 8 key
// tiles of 64. 48KB static smem: Qs + (Ks reused as Ps) + Vs.
// ---------------------------------------------------------------------------
__global__ void attn_kernel(const float* __restrict__ q, const float* __restrict__ k,
                            const float* __restrict__ v, const int* __restrict__ xtok,
                            const int* __restrict__ ltp, float* __restrict__ o) {
    __shared__ __align__(16) float Qs[64 * 64];   // [d][qi]
    __shared__ __align__(16) float KP[64 * 64];   // Ks [d][kj], then Ps [qi][kk]
    __shared__ __align__(16) float Vs[64 * 64];   // [kk][d]

    const int tid = threadIdx.x;
    const int tx = tid & 15, ty = tid >> 4;
    const int b = blockIdx.z, hh = blockIdx.y, qt = blockIdx.x;
    const int lt = ltp[0];

    const size_t qbase = ((size_t)(b * kS + qt * 64)) * kD + hh * 64;
    #pragma unroll
    for (int it = 0; it < 4; it++) {
        int idx = tid + it * 256;               // 0..1023
        int qi = idx >> 4, d4 = (idx & 15) * 4;
        float4 t4 = *(const float4*)(q + qbase + (size_t)qi * kD + d4);
        Qs[(d4 + 0) * 64 + qi] = t4.x;
        Qs[(d4 + 1) * 64 + qi] = t4.y;
        Qs[(d4 + 2) * 64 + qi] = t4.z;
        Qs[(d4 + 3) * 64 + qi] = t4.w;
    }

    float m_[4], l_[4], accO[4][4];
    #pragma unroll
    for (int i = 0; i < 4; i++) {
        m_[i] = -INFINITY; l_[i] = 0.0f;
        #pragma unroll
        for (int j = 0; j < 4; j++) accO[i][j] = 0.0f;
    }
    const int qrow0 = qt * 64 + ty * 4;

    for (int kt = 0; kt < 8; kt++) {
        const size_t kbase = ((size_t)(b * kS + kt * 64)) * kD + hh * 64;
        #pragma unroll
        for (int it = 0; it < 4; it++) {
            int idx = tid + it * 256;
            int kj = idx >> 4, d4 = (idx & 15) * 4;
            float4 t4 = *(const float4*)(k + kbase + (size_t)kj * kD + d4);
            KP[(d4 + 0) * 64 + kj] = t4.x;
            KP[(d4 + 1) * 64 + kj] = t4.y;
            KP[(d4 + 2) * 64 + kj] = t4.z;
            KP[(d4 + 3) * 64 + kj] = t4.w;
            *(float4*)&Vs[kj * 64 + d4] = *(const float4*)(v + kbase + (size_t)kj * kD + d4);
        }
        __syncthreads();

        float sv[4][4];
        #pragma unroll
        for (int i = 0; i < 4; i++)
            #pragma unroll
            for (int j = 0; j < 4; j++) sv[i][j] = 0.0f;

        for (int d = 0; d < 64; d++) {
            float qa[4];
            #pragma unroll
            for (int i = 0; i < 4; i++) qa[i] = Qs[d * 64 + ty * 4 + i];
            float4 kb = *(const float4*)&KP[d * 64 + tx * 4];
            #pragma unroll
            for (int i = 0; i < 4; i++) {
                sv[i][0] += qa[i] * kb.x;
                sv[i][1] += qa[i] * kb.y;
                sv[i][2] += qa[i] * kb.z;
                sv[i][3] += qa[i] * kb.w;
            }
        }

        // mask + scale: allowed = (k<=q || k<len_traj) && x[b,k]>0 ; masked -> -1e9
        const int* xr = xtok + b * kS + kt * 64;
        #pragma unroll
        for (int j = 0; j < 4; j++) {
            int kc = kt * 64 + tx * 4 + j;
            bool padj = xr[tx * 4 + j] > 0;
            #pragma unroll
            for (int i = 0; i < 4; i++) {
                bool ok = padj && ((kc <= qrow0 + i) || (kc < lt));
                sv[i][j] = ok ? sv[i][j] * 0.125f : -1.0e9f;
            }
        }

        // online softmax update (row reduction over the 16 tx lanes)
        #pragma unroll
        for (int i = 0; i < 4; i++) {
            float tm = fmaxf(fmaxf(sv[i][0], sv[i][1]), fmaxf(sv[i][2], sv[i][3]));
            #pragma unroll
            for (int off = 8; off > 0; off >>= 1)
                tm = fmaxf(tm, __shfl_xor_sync(0xffffffffu, tm, off));
            float nm = fmaxf(m_[i], tm);
            float al = expf(m_[i] - nm);
            float ts = 0.0f;
            #pragma unroll
            for (int j = 0; j < 4; j++) {
                float p = expf(sv[i][j] - nm);
                sv[i][j] = p;
                ts += p;
            }
            #pragma unroll
            for (int off = 8; off > 0; off >>= 1)
                ts += __shfl_xor_sync(0xffffffffu, ts, off);
            l_[i] = l_[i] * al + ts;
            m_[i] = nm;
            #pragma unroll
            for (int j = 0; j < 4; j++) accO[i][j] *= al;
        }
        __syncthreads();                       // done reading KP as K

        #pragma unroll
        for (int i = 0; i < 4; i++)
            #pragma unroll
            for (int j = 0; j < 4; j++)
                KP[(ty * 4 + i) * 64 + tx * 4 + j] = sv[i][j];
        __syncthreads();

        for (int kk = 0; kk < 64; kk++) {
            float pa[4];
            #pragma unroll
            for (int i = 0; i < 4; i++) pa[i] = KP[(ty * 4 + i) * 64 + kk];
            float4 vb = *(const float4*)&Vs[kk * 64 + tx * 4];
            #pragma unroll
            for (int i = 0; i < 4; i++) {
                accO[i][0] += pa[i] * vb.x;
                accO[i][1] += pa[i] * vb.y;
                accO[i][2] += pa[i] * vb.z;
                accO[i][3] += pa[i] * vb.w;
            }
        }
        __syncthreads();                       // before next tile overwrites KP/Vs
    }

    #pragma unroll
    for (int i = 0; i < 4; i++) {
        float inv = 1.0f / l_[i];
        float4 r;
        r.x = accO[i][0] * inv; r.y = accO[i][1] * inv;
        r.z = accO[i][2] * inv; r.w = accO[i][3] * inv;
        *(float4*)(o + ((size_t)(b * kS + qt * 64 + ty * 4 + i)) * kD + hh * 64 + tx * 4) = r;
    }
}

// ---------------------------------------------------------------------------
__global__ void copy_kernel(const float* __restrict__ in, float* __restrict__ out) {
    int idx = blockIdx.x * blockDim.x + threadIdx.x;   // float4 index
    if (idx >= kM * kD / 4) return;
    ((float4*)out)[idx] = ((const float4*)in)[idx];
}

// ---------------------------------------------------------------------------
extern "C" void kernel_launch(void* const* d_in, const int* in_sizes, int n_in,
                              void* d_out, int out_size) {
    const int*   x        = (const int*)d_in[0];
    const int*   tim      = (const int*)d_in[1];
    const int*   len_traj = (const int*)d_in[2];
    const float* tok_emb  = (const float*)d_in[3];
    const float* time_emb = (const float*)d_in[4];
    const float* emb_g    = (const float*)d_in[5];
    const float* emb_b    = (const float*)d_in[6];
    const float* Wq = (const float*)d_in[7];
    const float* bq = (const float*)d_in[8];
    const float* Wk = (const float*)d_in[9];
    const float* bk = (const float*)d_in[10];
    const float* Wv = (const float*)d_in[11];
    const float* bv = (const float*)d_in[12];
    const float* Wo = (const float*)d_in[13];
    const float* bo = (const float*)d_in[14];
    const float* ln1_g = (const float*)d_in[15];
    const float* ln1_b = (const float*)d_in[16];
    const float* W1 = (const float*)d_in[17];
    const float* b1 = (const float*)d_in[18];
    const float* W2 = (const float*)d_in[19];
    const float* b2 = (const float*)d_in[20];
    const float* ln2_g = (const float*)d_in[21];
    const float* ln2_b = (const float*)d_in[22];
    float* out = (float*)d_out;

    float *ph, *phn, *pq, *pk, *pv, *po, *pff, *ppe;
    cudaGetSymbolAddress((void**)&ph,  g_h);
    cudaGetSymbolAddress((void**)&phn, g_hn);
    cudaGetSymbolAddress((void**)&pq,  g_q);
    cudaGetSymbolAddress((void**)&pk,  g_k);
    cudaGetSymbolAddress((void**)&pv,  g_v);
    cudaGetSymbolAddress((void**)&po,  g_o);
    cudaGetSymbolAddress((void**)&pff, g_ff);
    cudaGetSymbolAddress((void**)&ppe, g_pe);

    pe_kernel<<<(kS * kD + 255) / 256, 256>>>(ppe);
    embed_kernel<<<(kM * kD + 255) / 256, 256>>>(x, tim, tok_emb, time_emb, ppe, phn);
    ln_kernel<<<kM, 256>>>(phn, ph, emb_g, emb_b);

    const dim3 gProj(kD / 128, kM / 128);     // N=768
    const dim3 gFF1(kFF / 128, kM / 128);     // N=3072
    const dim3 gAttn(kS / 64, kH, kB);

    for (int i = 0; i < kL; i++) {
        ln_kernel<<<kM, 256>>>(ph, phn, ln1_g + i * kD, ln1_b + i * kD);
        sgemm_kernel<<<gProj, 256>>>(phn, Wq + (size_t)i * kD * kD, bq + i * kD,
                                     nullptr, pq, kM, kD, kD, 0);
        sgemm_kernel<<<gProj, 256>>>(phn, Wk + (size_t)i * kD * kD, bk + i * kD,
                                     nullptr, pk, kM, kD, kD, 0);
        sgemm_kernel<<<gProj, 256>>>(phn, Wv + (size_t)i * kD * kD, bv + i * kD,
                                     nullptr, pv, kM, kD, kD, 0);
        attn_kernel<<<gAttn, 256>>>(pq, pk, pv, x, len_traj, po);
        sgemm_kernel<<<gProj, 256>>>(po, Wo + (size_t)i * kD * kD, bo + i * kD,
                                     ph, ph, kM, kD, kD, 0);
        ln_kernel<<<kM, 256>>>(ph, phn, ln2_g + i * kD, ln2_b + i * kD);
        sgemm_kernel<<<gFF1, 256>>>(phn, W1 + (size_t)i * kD * kFF, b1 + i * kFF,
                                    nullptr, pff, kM, kFF, kD, 1);
        sgemm_kernel<<<gProj, 256>>>(pff, W2 + (size_t)i * kFF * kD, b2 + i * kD,
                                     ph, ph, kM, kD, kFF, 0);
    }

    copy_kernel<<<(kM * kD / 4 + 255) / 256, 256>>>(ph, out);
}

// round 4
// speedup vs baseline: 2.1604x; 2.1604x over previous
#include <cuda_runtime.h>
#include <cuda_bf16.h>
#include <math.h>
#include <stdint.h>

// ---------------------------------------------------------------------------
// Bert_Traj_Model: B=32, S=512, D=768, H=12, dh=64, FF=3072, L=12, fp32 I/O.
// Round 3: fix B-operand ldmatrix (non-trans for [n][k] storage). GEMMs on
// mma.sync.m16n8k16 bf16 with 3-term split precision (hi*hi+hi*lo+lo*hi).
// ---------------------------------------------------------------------------

namespace {
constexpr int kB  = 32;
constexpr int kS  = 512;
constexpr int kD  = 768;
constexpr int kH  = 12;
constexpr int kFF = 3072;
constexpr int kL  = 12;
constexpr int kM  = kB * kS;               // 16384 rows
constexpr int kStageBytes = 32768;         // Ahi,Alo,Bhi,Blo 8KB each
constexpr int kNS = 3;
constexpr int kSmemBytes = kNS * kStageBytes;   // 96KB
}

// ----------------------------- scratch (no allocs allowed) ------------------
__device__ float g_h [(size_t)kM * kD];
__device__ float g_q [(size_t)kM * kD];
__device__ float g_k [(size_t)kM * kD];
__device__ float g_v [(size_t)kM * kD];
__device__ float g_pe[kS * kD];
__device__ __nv_bfloat16 g_hn_hi[(size_t)kM * kD];
__device__ __nv_bfloat16 g_hn_lo[(size_t)kM * kD];
__device__ __nv_bfloat16 g_o_hi [(size_t)kM * kD];
__device__ __nv_bfloat16 g_o_lo [(size_t)kM * kD];
__device__ __nv_bfloat16 g_ff_hi[(size_t)kM * kFF];
__device__ __nv_bfloat16 g_ff_lo[(size_t)kM * kFF];
// pre-split, pre-tiled weights: blocks of 128(n) x 32(k), row-major in block
__device__ __nv_bfloat16 g_wq_hi[(size_t)kL * kD * kD];
__device__ __nv_bfloat16 g_wq_lo[(size_t)kL * kD * kD];
__device__ __nv_bfloat16 g_wk_hi[(size_t)kL * kD * kD];
__device__ __nv_bfloat16 g_wk_lo[(size_t)kL * kD * kD];
__device__ __nv_bfloat16 g_wv_hi[(size_t)kL * kD * kD];
__device__ __nv_bfloat16 g_wv_lo[(size_t)kL * kD * kD];
__device__ __nv_bfloat16 g_wo_hi[(size_t)kL * kD * kD];
__device__ __nv_bfloat16 g_wo_lo[(size_t)kL * kD * kD];
__device__ __nv_bfloat16 g_w1_hi[(size_t)kL * kD * kFF];
__device__ __nv_bfloat16 g_w1_lo[(size_t)kL * kD * kFF];
__device__ __nv_bfloat16 g_w2_hi[(size_t)kL * kFF * kD];
__device__ __nv_bfloat16 g_w2_lo[(size_t)kL * kFF * kD];

// ----------------------------- PTX helpers ---------------------------------
__device__ __forceinline__ uint32_t smem_u32(const void* p) {
    uint32_t a;
    asm("{ .reg .u64 t; cvta.to.shared.u64 t, %1; cvt.u32.u64 %0, t; }" : "=r"(a) : "l"(p));
    return a;
}
#define CP16(dst, src) asm volatile("cp.async.cg.shared.global [%0], [%1], 16;" :: "r"(dst), "l"(src))
#define CP_COMMIT()    asm volatile("cp.async.commit_group;" ::: "memory")
#define CP_WAIT(n)     asm volatile("cp.async.wait_group %0;" :: "n"(n) : "memory")

#define LDSM4(r0, r1, r2, r3, a)                                                \
    asm volatile("ldmatrix.sync.aligned.m8n8.x4.shared.b16 {%0,%1,%2,%3}, [%4];" \
                 : "=r"(r0), "=r"(r1), "=r"(r2), "=r"(r3) : "r"(a))
#define MMA_BF16(d, a, b)                                                       \
    asm volatile("mma.sync.aligned.m16n8k16.row.col.f32.bf16.bf16.f32 "         \
                 "{%0,%1,%2,%3}, {%4,%5,%6,%7}, {%8,%9}, {%0,%1,%2,%3};"        \
                 : "+f"((d)[0]), "+f"((d)[1]), "+f"((d)[2]), "+f"((d)[3])       \
                 : "r"((a)[0]), "r"((a)[1]), "r"((a)[2]), "r"((a)[3]),          \
                   "r"((b)[0]), "r"((b)[1]))

__device__ __forceinline__ void bsplit(float v, __nv_bfloat16& h, __nv_bfloat16& l) {
    h = __float2bfloat16(v);
    l = __float2bfloat16(v - __bfloat162float(h));
}
__device__ __forceinline__ uint32_t soff(int row, int ch) {
    return (uint32_t)(row * 64 + ((ch ^ ((row >> 1) & 3)) << 4));
}

// ---------------------------------------------------------------------------
// Weight prep: W[L][K][N] fp32 -> bf16 hi/lo, tile-major blocks:
//   block(nt, kc) = 128x32, elem (nl, kk) at nl*32 + kk.
// ---------------------------------------------------------------------------
__global__ void prep_w_kernel(const float* __restrict__ W, __nv_bfloat16* __restrict__ hi,
                              __nv_bfloat16* __restrict__ lo, int K, int N) {
    size_t total = (size_t)kL * K * N;
    int kcnt = K / 32;
    for (size_t idx = (size_t)blockIdx.x * blockDim.x + threadIdx.x; idx < total;
         idx += (size_t)gridDim.x * blockDim.x) {
        size_t per = (size_t)K * N;
        int l = (int)(idx / per);
        int rem = (int)(idx - (size_t)l * per);
        int k = rem / N, n = rem - k * N;
        float v = W[idx];
        __nv_bfloat16 h, lw;
        bsplit(v, h, lw);
        int nt = n >> 7, nl = n & 127, kc = k >> 5, kk = k & 31;
        size_t dst = (size_t)l * per + ((size_t)(nt * kcnt + kc)) * 4096 + nl * 32 + kk;
        hi[dst] = h;
        lo[dst] = lw;
    }
}

// ---------------------------------------------------------------------------
// mma_gemm: C[M,N] = epilogue(A @ W + bias). A row-major bf16 hi/lo,
// W pre-tiled bf16 hi/lo. mode: 0=plain fp32, 1=+Res fp32, 2=relu+bf16 split.
// grid (N/128, M/128), 256 threads, 96KB dyn smem.
// ---------------------------------------------------------------------------
__global__ void __launch_bounds__(256, 1)
mma_gemm(const __nv_bfloat16* __restrict__ Ahi, const __nv_bfloat16* __restrict__ Alo,
         const __nv_bfloat16* __restrict__ Bhi, const __nv_bfloat16* __restrict__ Blo,
         const float* __restrict__ bias, const float* __restrict__ Res,
         float* __restrict__ C, __nv_bfloat16* __restrict__ Chi,
         __nv_bfloat16* __restrict__ Clo, int N, int K, int mode) {
    extern __shared__ char smem[];
    const uint32_t sb = smem_u32(smem);
    const int tid = threadIdx.x;
    const int lane = tid & 31, wid = tid >> 5;
    const int wm = (wid & 1) * 64, wn = (wid >> 1) * 32;
    const int m0 = blockIdx.y * 128, n0 = blockIdx.x * 128;
    const int iters = K >> 5;
    const size_t btile = (size_t)blockIdx.x * iters * 4096;

    float acc[4][4][4];
    #pragma unroll
    for (int a = 0; a < 4; a++)
        #pragma unroll
        for (int b = 0; b < 4; b++)
            #pragma unroll
            for (int c = 0; c < 4; c++) acc[a][b][c] = 0.0f;

    auto load_stage = [&](int c, int s) {
        const uint32_t st = sb + (uint32_t)s * kStageBytes;
        #pragma unroll
        for (int p = 0; p < 2; p++) {
            int idx = p * 256 + tid;
            int row = idx >> 2, ch = idx & 3;
            uint32_t so = soff(row, ch);
            const __nv_bfloat16* gAh = Ahi + (size_t)(m0 + row) * K + c * 32 + ch * 8;
            const __nv_bfloat16* gAl = Alo + (size_t)(m0 + row) * K + c * 32 + ch * 8;
            size_t boff = btile + (size_t)c * 4096 + row * 32 + ch * 8;
            CP16(st + so, gAh);
            CP16(st + 8192 + so, gAl);
            CP16(st + 16384 + so, Bhi + boff);
            CP16(st + 24576 + so, Blo + boff);
        }
        CP_COMMIT();
    };

    auto compute_stage = [&](int s) {
        const uint32_t base = sb + (uint32_t)s * kStageBytes;
        #pragma unroll
        for (int ks = 0; ks < 2; ks++) {
            const int kc = ks * 2;
            uint32_t ah[4][4], al[4][4], bh[4][2], bl[4][2];
            #pragma unroll
            for (int mf = 0; mf < 4; mf++) {
                int row = wm + mf * 16 + (lane & 15);
                int ch = kc + (lane >> 4);
                uint32_t so = soff(row, ch);
                LDSM4(ah[mf][0], ah[mf][1], ah[mf][2], ah[mf][3], base + so);
                LDSM4(al[mf][0], al[mf][1], al[mf][2], al[mf][3], base + 8192 + so);
            }
            #pragma unroll
            for (int nb = 0; nb < 2; nb++) {
                int row = wn + nb * 16 + (lane & 7) + ((lane >> 4) << 3);
                int ch = kc + ((lane >> 3) & 1);
                uint32_t so = soff(row, ch);
                // B stored [n][k] (k contiguous) -> NON-trans ldmatrix gives the
                // m16n8k16 col-operand fragment (thread t: n=t/4, k=(t%4)*2,+1).
                LDSM4(bh[2 * nb][0], bh[2 * nb][1], bh[2 * nb + 1][0], bh[2 * nb + 1][1],
                      base + 16384 + so);
                LDSM4(bl[2 * nb][0], bl[2 * nb][1], bl[2 * nb + 1][0], bl[2 * nb + 1][1],
                      base + 24576 + so);
            }
            #pragma unroll
            for (int mf = 0; mf < 4; mf++)
                #pragma unroll
                for (int nf = 0; nf < 4; nf++) {
                    MMA_BF16(acc[mf][nf], ah[mf], bh[nf]);
                    MMA_BF16(acc[mf][nf], ah[mf], bl[nf]);
                    MMA_BF16(acc[mf][nf], al[mf], bh[nf]);
                }
        }
    };

    load_stage(0, 0);
    load_stage(1, 1);

    for (int c = 0; c < iters; c++) {
        const int s = c - (c / kNS) * kNS;
        if (c + 2 < iters) {
            int s2 = (c + 2) % kNS;
            load_stage(c + 2, s2);
            CP_WAIT(2);
        } else if (c + 1 < iters) {
            CP_WAIT(1);
        } else {
            CP_WAIT(0);
        }
        __syncthreads();
        compute_stage(s);
        __syncthreads();
    }

    // epilogue
    #pragma unroll
    for (int mf = 0; mf < 4; mf++) {
        #pragma unroll
        for (int h = 0; h < 2; h++) {
            const int r = m0 + wm + mf * 16 + (lane >> 2) + h * 8;
            #pragma unroll
            for (int nf = 0; nf < 4; nf++) {
                const int cc = n0 + wn + nf * 8 + (lane & 3) * 2;
                float v0 = acc[mf][nf][h * 2 + 0] + bias[cc];
                float v1 = acc[mf][nf][h * 2 + 1] + bias[cc + 1];
                size_t base = (size_t)r * N + cc;
                if (mode == 2) {
                    v0 = fmaxf(v0, 0.0f);
                    v1 = fmaxf(v1, 0.0f);
                    __nv_bfloat16 h0, l0, h1, l1;
                    bsplit(v0, h0, l0);
                    bsplit(v1, h1, l1);
                    *(__nv_bfloat162*)(Chi + base) = __halves2bfloat162(h0, h1);
                    *(__nv_bfloat162*)(Clo + base) = __halves2bfloat162(l0, l1);
                } else if (mode == 1) {
                    float2 rr = *(const float2*)(Res + base);
                    float2 o;
                    o.x = v0 + rr.x;
                    o.y = v1 + rr.y;
                    *(float2*)(C + base) = o;
                } else {
                    float2 o;
                    o.x = v0;
                    o.y = v1;
                    *(float2*)(C + base) = o;
                }
            }
        }
    }
}

// ---------------------------------------------------------------------------
// Positional encoding (fp64 for exactness).
// ---------------------------------------------------------------------------
__global__ void pe_kernel(float* __restrict__ pe) {
    int idx = blockIdx.x * blockDim.x + threadIdx.x;
    if (idx >= kS * kD) return;
    int s = idx / kD;
    int j = idx - s * kD;
    int i2 = j & ~1;
    double ang = (double)s * pow(10000.0, -(double)i2 / (double)kD);
    pe[idx] = (j & 1) ? (float)cos(ang) : (float)sin(ang);
}

__global__ void embed_kernel(const int* __restrict__ x, const int* __restrict__ tim,
                             const float* __restrict__ tok_emb,
                             const float* __restrict__ time_emb,
                             const float* __restrict__ pe, float* __restrict__ out) {
    int idx = blockIdx.x * blockDim.x + threadIdx.x;
    if (idx >= kM * kD) return;
    int bs = idx / kD;
    int j = idx - bs * kD;
    int s = bs & (kS - 1);
    out[idx] = tok_emb[(size_t)x[bs] * kD + j] + time_emb[(size_t)tim[bs] * kD + j]
             + pe[s * kD + j];
}

// ----------------------------- LayerNorm ------------------------------------
__device__ __forceinline__ float block_reduce_sum(float v, float* sred) {
    #pragma unroll
    for (int o = 16; o > 0; o >>= 1) v += __shfl_xor_sync(0xffffffffu, v, o);
    int w = threadIdx.x >> 5;
    __syncthreads();
    if ((threadIdx.x & 31) == 0) sred[w] = v;
    __syncthreads();
    if (threadIdx.x == 0) {
        float t = sred[0];
        #pragma unroll
        for (int i = 1; i < 8; i++) t += sred[i];
        sred[0] = t;
    }
    __syncthreads();
    return sred[0];
}

__global__ void ln_kernel(const float* __restrict__ in, float* __restrict__ out,
                          const float* __restrict__ g, const float* __restrict__ b) {
    __shared__ float sred[8];
    int row = blockIdx.x, tid = threadIdx.x;
    const float* ip = in + (size_t)row * kD;
    float v0 = ip[tid], v1 = ip[tid + 256], v2 = ip[tid + 512];
    float sum = block_reduce_sum(v0 + v1 + v2, sred);
    float mu = sum * (1.0f / 768.0f);
    float d0 = v0 - mu, d1 = v1 - mu, d2 = v2 - mu;
    float sq = block_reduce_sum(d0 * d0 + d1 * d1 + d2 * d2, sred);
    float inv = 1.0f / sqrtf(sq * (1.0f / 768.0f) + 1e-6f);
    float* op = out + (size_t)row * kD;
    op[tid]       = g[tid]       * d0 * inv + b[tid];
    op[tid + 256] = g[tid + 256] * d1 * inv + b[tid + 256];
    op[tid + 512] = g[tid + 512] * d2 * inv + b[tid + 512];
}

__global__ void ln_split_kernel(const float* __restrict__ in,
                                __nv_bfloat16* __restrict__ ohi,
                                __nv_bfloat16* __restrict__ olo,
                                const float* __restrict__ g, const float* __restrict__ b) {
    __shared__ float sred[8];
    int row = blockIdx.x, tid = threadIdx.x;
    const float* ip = in + (size_t)row * kD;
    float v0 = ip[tid], v1 = ip[tid + 256], v2 = ip[tid + 512];
    float sum = block_reduce_sum(v0 + v1 + v2, sred);
    float mu = sum * (1.0f / 768.0f);
    float d0 = v0 - mu, d1 = v1 - mu, d2 = v2 - mu;
    float sq = block_reduce_sum(d0 * d0 + d1 * d1 + d2 * d2, sred);
    float inv = 1.0f / sqrtf(sq * (1.0f / 768.0f) + 1e-6f);
    size_t base = (size_t)row * kD;
    float r0 = g[tid] * d0 * inv + b[tid];
    float r1 = g[tid + 256] * d1 * inv + b[tid + 256];
    float r2 = g[tid + 512] * d2 * inv + b[tid + 512];
    __nv_bfloat16 h, l;
    bsplit(r0, h, l); ohi[base + tid]       = h; olo[base + tid]       = l;
    bsplit(r1, h, l); ohi[base + tid + 256] = h; olo[base + tid + 256] = l;
    bsplit(r2, h, l); ohi[base + tid + 512] = h; olo[base + tid + 512] = l;
}

// ---------------------------------------------------------------------------
// Attention (SIMT flash) with bf16-split epilogue.
// ---------------------------------------------------------------------------
__global__ void attn_kernel(const float* __restrict__ q, const float* __restrict__ k,
                            const float* __restrict__ v, const int* __restrict__ xtok,
                            const int* __restrict__ ltp,
                            __nv_bfloat16* __restrict__ ohi,
                            __nv_bfloat16* __restrict__ olo) {
    __shared__ __align__(16) float Qs[64 * 64];
    __shared__ __align__(16) float KP[64 * 64];
    __shared__ __align__(16) float Vs[64 * 64];

    const int tid = threadIdx.x;
    const int tx = tid & 15, ty = tid >> 4;
    const int b = blockIdx.z, hh = blockIdx.y, qt = blockIdx.x;
    const int lt = ltp[0];

    const size_t qbase = ((size_t)(b * kS + qt * 64)) * kD + hh * 64;
    #pragma unroll
    for (int it = 0; it < 4; it++) {
        int idx = tid + it * 256;
        int qi = idx >> 4, d4 = (idx & 15) * 4;
        float4 t4 = *(const float4*)(q + qbase + (size_t)qi * kD + d4);
        Qs[(d4 + 0) * 64 + qi] = t4.x;
        Qs[(d4 + 1) * 64 + qi] = t4.y;
        Qs[(d4 + 2) * 64 + qi] = t4.z;
        Qs[(d4 + 3) * 64 + qi] = t4.w;
    }

    float m_[4], l_[4], accO[4][4];
    #pragma unroll
    for (int i = 0; i < 4; i++) {
        m_[i] = -INFINITY; l_[i] = 0.0f;
        #pragma unroll
        for (int j = 0; j < 4; j++) accO[i][j] = 0.0f;
    }
    const int qrow0 = qt * 64 + ty * 4;

    for (int kt = 0; kt < 8; kt++) {
        const size_t kbase = ((size_t)(b * kS + kt * 64)) * kD + hh * 64;
        #pragma unroll
        for (int it = 0; it < 4; it++) {
            int idx = tid + it * 256;
            int kj = idx >> 4, d4 = (idx & 15) * 4;
            float4 t4 = *(const float4*)(k + kbase + (size_t)kj * kD + d4);
            KP[(d4 + 0) * 64 + kj] = t4.x;
            KP[(d4 + 1) * 64 + kj] = t4.y;
            KP[(d4 + 2) * 64 + kj] = t4.z;
            KP[(d4 + 3) * 64 + kj] = t4.w;
            *(float4*)&Vs[kj * 64 + d4] = *(const float4*)(v + kbase + (size_t)kj * kD + d4);
        }
        __syncthreads();

        float sv[4][4];
        #pragma unroll
        for (int i = 0; i < 4; i++)
            #pragma unroll
            for (int j = 0; j < 4; j++) sv[i][j] = 0.0f;

        for (int d = 0; d < 64; d++) {
            float qa[4];
            #pragma unroll
            for (int i = 0; i < 4; i++) qa[i] = Qs[d * 64 + ty * 4 + i];
            float4 kb = *(const float4*)&KP[d * 64 + tx * 4];
            #pragma unroll
            for (int i = 0; i < 4; i++) {
                sv[i][0] += qa[i] * kb.x;
                sv[i][1] += qa[i] * kb.y;
                sv[i][2] += qa[i] * kb.z;
                sv[i][3] += qa[i] * kb.w;
            }
        }

        const int* xr = xtok + b * kS + kt * 64;
        #pragma unroll
        for (int j = 0; j < 4; j++) {
            int kc = kt * 64 + tx * 4 + j;
            bool padj = xr[tx * 4 + j] > 0;
            #pragma unroll
            for (int i = 0; i < 4; i++) {
                bool ok = padj && ((kc <= qrow0 + i) || (kc < lt));
                sv[i][j] = ok ? sv[i][j] * 0.125f : -1.0e9f;
            }
        }

        #pragma unroll
        for (int i = 0; i < 4; i++) {
            float tm = fmaxf(fmaxf(sv[i][0], sv[i][1]), fmaxf(sv[i][2], sv[i][3]));
            #pragma unroll
            for (int off = 8; off > 0; off >>= 1)
                tm = fmaxf(tm, __shfl_xor_sync(0xffffffffu, tm, off));
            float nm = fmaxf(m_[i], tm);
            float al = expf(m_[i] - nm);
            float ts = 0.0f;
            #pragma unroll
            for (int j = 0; j < 4; j++) {
                float p = expf(sv[i][j] - nm);
                sv[i][j] = p;
                ts += p;
            }
            #pragma unroll
            for (int off = 8; off > 0; off >>= 1)
                ts += __shfl_xor_sync(0xffffffffu, ts, off);
            l_[i] = l_[i] * al + ts;
            m_[i] = nm;
            #pragma unroll
            for (int j = 0; j < 4; j++) accO[i][j] *= al;
        }
        __syncthreads();

        #pragma unroll
        for (int i = 0; i < 4; i++)
            #pragma unroll
            for (int j = 0; j < 4; j++)
                KP[(ty * 4 + i) * 64 + tx * 4 + j] = sv[i][j];
        __syncthreads();

        for (int kk = 0; kk < 64; kk++) {
            float pa[4];
            #pragma unroll
            for (int i = 0; i < 4; i++) pa[i] = KP[(ty * 4 + i) * 64 + kk];
            float4 vb = *(const float4*)&Vs[kk * 64 + tx * 4];
            #pragma unroll
            for (int i = 0; i < 4; i++) {
                accO[i][0] += pa[i] * vb.x;
                accO[i][1] += pa[i] * vb.y;
                accO[i][2] += pa[i] * vb.z;
                accO[i][3] += pa[i] * vb.w;
            }
        }
        __syncthreads();
    }

    #pragma unroll
    for (int i = 0; i < 4; i++) {
        float inv = 1.0f / l_[i];
        size_t base = ((size_t)(b * kS + qt * 64 + ty * 4 + i)) * kD + hh * 64 + tx * 4;
        #pragma unroll
        for (int j = 0; j < 4; j++) {
            __nv_bfloat16 h, l;
            bsplit(accO[i][j] * inv, h, l);
            ohi[base + j] = h;
            olo[base + j] = l;
        }
    }
}

__global__ void copy_kernel(const float* __restrict__ in, float* __restrict__ out) {
    int idx = blockIdx.x * blockDim.x + threadIdx.x;
    if (idx >= kM * kD / 4) return;
    ((float4*)out)[idx] = ((const float4*)in)[idx];
}

// ---------------------------------------------------------------------------
extern "C" void kernel_launch(void* const* d_in, const int* in_sizes, int n_in,
                              void* d_out, int out_size) {
    const int*   x        = (const int*)d_in[0];
    const int*   tim      = (const int*)d_in[1];
    const int*   len_traj = (const int*)d_in[2];
    const float* tok_emb  = (const float*)d_in[3];
    const float* time_emb = (const float*)d_in[4];
    const float* emb_g    = (const float*)d_in[5];
    const float* emb_b    = (const float*)d_in[6];
    const float* Wq = (const float*)d_in[7];
    const float* bq = (const float*)d_in[8];
    const float* Wk = (const float*)d_in[9];
    const float* bk = (const float*)d_in[10];
    const float* Wv = (const float*)d_in[11];
    const float* bv = (const float*)d_in[12];
    const float* Wo = (const float*)d_in[13];
    const float* bo = (const float*)d_in[14];
    const float* ln1_g = (const float*)d_in[15];
    const float* ln1_b = (const float*)d_in[16];
    const float* W1 = (const float*)d_in[17];
    const float* b1 = (const float*)d_in[18];
    const float* W2 = (const float*)d_in[19];
    const float* b2 = (const float*)d_in[20];
    const float* ln2_g = (const float*)d_in[21];
    const float* ln2_b = (const float*)d_in[22];
    float* out = (float*)d_out;

    float *ph, *pq, *pk, *pv, *ppe;
    __nv_bfloat16 *phnh, *phnl, *pohi, *polo, *pffh, *pffl;
    __nv_bfloat16 *wqh, *wql, *wkh, *wkl, *wvh, *wvl, *woh, *wol, *w1h, *w1l, *w2h, *w2l;
    cudaGetSymbolAddress((void**)&ph,   g_h);
    cudaGetSymbolAddress((void**)&pq,   g_q);
    cudaGetSymbolAddress((void**)&pk,   g_k);
    cudaGetSymbolAddress((void**)&pv,   g_v);
    cudaGetSymbolAddress((void**)&ppe,  g_pe);
    cudaGetSymbolAddress((void**)&phnh, g_hn_hi);
    cudaGetSymbolAddress((void**)&phnl, g_hn_lo);
    cudaGetSymbolAddress((void**)&pohi, g_o_hi);
    cudaGetSymbolAddress((void**)&polo, g_o_lo);
    cudaGetSymbolAddress((void**)&pffh, g_ff_hi);
    cudaGetSymbolAddress((void**)&pffl, g_ff_lo);
    cudaGetSymbolAddress((void**)&wqh, g_wq_hi);
    cudaGetSymbolAddress((void**)&wql, g_wq_lo);
    cudaGetSymbolAddress((void**)&wkh, g_wk_hi);
    cudaGetSymbolAddress((void**)&wkl, g_wk_lo);
    cudaGetSymbolAddress((void**)&wvh, g_wv_hi);
    cudaGetSymbolAddress((void**)&wvl, g_wv_lo);
    cudaGetSymbolAddress((void**)&woh, g_wo_hi);
    cudaGetSymbolAddress((void**)&wol, g_wo_lo);
    cudaGetSymbolAddress((void**)&w1h, g_w1_hi);
    cudaGetSymbolAddress((void**)&w1l, g_w1_lo);
    cudaGetSymbolAddress((void**)&w2h, g_w2_hi);
    cudaGetSymbolAddress((void**)&w2l, g_w2_lo);

    cudaFuncSetAttribute(mma_gemm, cudaFuncAttributeMaxDynamicSharedMemorySize, kSmemBytes);

    prep_w_kernel<<<4096, 256>>>(Wq, wqh, wql, kD, kD);
    prep_w_kernel<<<4096, 256>>>(Wk, wkh, wkl, kD, kD);
    prep_w_kernel<<<4096, 256>>>(Wv, wvh, wvl, kD, kD);
    prep_w_kernel<<<4096, 256>>>(Wo, woh, wol, kD, kD);
    prep_w_kernel<<<8192, 256>>>(W1, w1h, w1l, kD, kFF);
    prep_w_kernel<<<8192, 256>>>(W2, w2h, w2l, kFF, kD);

    pe_kernel<<<(kS * kD + 255) / 256, 256>>>(ppe);
    embed_kernel<<<(kM * kD + 255) / 256, 256>>>(x, tim, tok_emb, time_emb, ppe, pq);
    ln_kernel<<<kM, 256>>>(pq, ph, emb_g, emb_b);

    const dim3 gProj(kD / 128, kM / 128);
    const dim3 gFF1(kFF / 128, kM / 128);
    const dim3 gAttn(kS / 64, kH, kB);

    for (int i = 0; i < kL; i++) {
        const size_t wD = (size_t)i * kD * kD;
        const size_t wF = (size_t)i * kD * kFF;
        ln_split_kernel<<<kM, 256>>>(ph, phnh, phnl, ln1_g + i * kD, ln1_b + i * kD);
        mma_gemm<<<gProj, 256, kSmemBytes>>>(phnh, phnl, wqh + wD, wql + wD, bq + i * kD,
                                             nullptr, pq, nullptr, nullptr, kD, kD, 0);
        mma_gemm<<<gProj, 256, kSmemBytes>>>(phnh, phnl, wkh + wD, wkl + wD, bk + i * kD,
                                             nullptr, pk, nullptr, nullptr, kD, kD, 0);
        mma_gemm<<<gProj, 256, kSmemBytes>>>(phnh, phnl, wvh + wD, wvl + wD, bv + i * kD,
                                             nullptr, pv, nullptr, nullptr, kD, kD, 0);
        attn_kernel<<<gAttn, 256>>>(pq, pk, pv, x, len_traj, pohi, polo);
        mma_gemm<<<gProj, 256, kSmemBytes>>>(pohi, polo, woh + wD, wol + wD, bo + i * kD,
                                             ph, ph, nullptr, nullptr, kD, kD, 1);
        ln_split_kernel<<<kM, 256>>>(ph, phnh, phnl, ln2_g + i * kD, ln2_b + i * kD);
        mma_gemm<<<gFF1, 256, kSmemBytes>>>(phnh, phnl, w1h + wF, w1l + wF, b1 + i * kFF,
                                            nullptr, nullptr, pffh, pffl, kFF, kD, 2);
        mma_gemm<<<gProj, 256, kSmemBytes>>>(pffh, pffl, w2h + wF, w2l + wF, b2 + i * kD,
                                             ph, ph, nullptr, nullptr, kD, kFF, 1);
    }

    copy_kernel<<<(kM * kD / 4 + 255) / 256, 256>>>(ph, out);
}

// round 5
// speedup vs baseline: 2.7292x; 1.2633x over previous
#include <cuda_runtime.h>
#include <cuda_bf16.h>
#include <math.h>
#include <stdint.h>

// ---------------------------------------------------------------------------
// Bert_Traj_Model: B=32, S=512, D=768, H=12, dh=64, FF=3072, L=12, fp32 I/O.
// Round 4: tensor-core flash attention (mma.m16n8k16 bf16, 3-term split),
// QKV GEMMs emit bf16 hi/lo directly (Q pre-scaled). GEMM core unchanged.
// ---------------------------------------------------------------------------

namespace {
constexpr int kB  = 32;
constexpr int kS  = 512;
constexpr int kD  = 768;
constexpr int kH  = 12;
constexpr int kFF = 3072;
constexpr int kL  = 12;
constexpr int kM  = kB * kS;               // 16384 rows
constexpr int kStageBytes = 32768;         // GEMM: Ahi,Alo,Bhi,Blo 8KB each
constexpr int kNS = 3;
constexpr int kSmemBytes = kNS * kStageBytes;   // 96KB
constexpr int kAttnSmem = 98816;           // Q 32K + 2 stages x 32K + pad 512
}

// ----------------------------- scratch (no allocs allowed) ------------------
__device__ float g_h  [(size_t)kM * kD];
__device__ float g_tmp[(size_t)kM * kD];
__device__ float g_pe [kS * kD];
__device__ __nv_bfloat16 g_hn_hi[(size_t)kM * kD];
__device__ __nv_bfloat16 g_hn_lo[(size_t)kM * kD];
__device__ __nv_bfloat16 g_q_hi [(size_t)kM * kD];
__device__ __nv_bfloat16 g_q_lo [(size_t)kM * kD];
__device__ __nv_bfloat16 g_k_hi [(size_t)kM * kD];
__device__ __nv_bfloat16 g_k_lo [(size_t)kM * kD];
__device__ __nv_bfloat16 g_v_hi [(size_t)kM * kD];
__device__ __nv_bfloat16 g_v_lo [(size_t)kM * kD];
__device__ __nv_bfloat16 g_o_hi [(size_t)kM * kD];
__device__ __nv_bfloat16 g_o_lo [(size_t)kM * kD];
__device__ __nv_bfloat16 g_ff_hi[(size_t)kM * kFF];
__device__ __nv_bfloat16 g_ff_lo[(size_t)kM * kFF];
// pre-split, pre-tiled weights: blocks of 128(n) x 32(k), row-major in block
__device__ __nv_bfloat16 g_wq_hi[(size_t)kL * kD * kD];
__device__ __nv_bfloat16 g_wq_lo[(size_t)kL * kD * kD];
__device__ __nv_bfloat16 g_wk_hi[(size_t)kL * kD * kD];
__device__ __nv_bfloat16 g_wk_lo[(size_t)kL * kD * kD];
__device__ __nv_bfloat16 g_wv_hi[(size_t)kL * kD * kD];
__device__ __nv_bfloat16 g_wv_lo[(size_t)kL * kD * kD];
__device__ __nv_bfloat16 g_wo_hi[(size_t)kL * kD * kD];
__device__ __nv_bfloat16 g_wo_lo[(size_t)kL * kD * kD];
__device__ __nv_bfloat16 g_w1_hi[(size_t)kL * kD * kFF];
__device__ __nv_bfloat16 g_w1_lo[(size_t)kL * kD * kFF];
__device__ __nv_bfloat16 g_w2_hi[(size_t)kL * kFF * kD];
__device__ __nv_bfloat16 g_w2_lo[(size_t)kL * kFF * kD];

// ----------------------------- PTX helpers ---------------------------------
__device__ __forceinline__ uint32_t smem_u32(const void* p) {
    uint32_t a;
    asm("{ .reg .u64 t; cvta.to.shared.u64 t, %1; cvt.u32.u64 %0, t; }" : "=r"(a) : "l"(p));
    return a;
}
#define CP16(dst, src) asm volatile("cp.async.cg.shared.global [%0], [%1], 16;" :: "r"(dst), "l"(src))
#define CP_COMMIT()    asm volatile("cp.async.commit_group;" ::: "memory")
#define CP_WAIT(n)     asm volatile("cp.async.wait_group %0;" :: "n"(n) : "memory")

#define LDSM4(r0, r1, r2, r3, a)                                                \
    asm volatile("ldmatrix.sync.aligned.m8n8.x4.shared.b16 {%0,%1,%2,%3}, [%4];" \
                 : "=r"(r0), "=r"(r1), "=r"(r2), "=r"(r3) : "r"(a))
#define LDSM4T(r0, r1, r2, r3, a)                                               \
    asm volatile("ldmatrix.sync.aligned.m8n8.x4.trans.shared.b16 {%0,%1,%2,%3}, [%4];" \
                 : "=r"(r0), "=r"(r1), "=r"(r2), "=r"(r3) : "r"(a))
#define MMA_BF16(d, a, b)                                                       \
    asm volatile("mma.sync.aligned.m16n8k16.row.col.f32.bf16.bf16.f32 "         \
                 "{%0,%1,%2,%3}, {%4,%5,%6,%7}, {%8,%9}, {%0,%1,%2,%3};"        \
                 : "+f"((d)[0]), "+f"((d)[1]), "+f"((d)[2]), "+f"((d)[3])       \
                 : "r"((a)[0]), "r"((a)[1]), "r"((a)[2]), "r"((a)[3]),          \
                   "r"((b)[0]), "r"((b)[1]))

__device__ __forceinline__ void bsplit(float v, __nv_bfloat16& h, __nv_bfloat16& l) {
    h = __float2bfloat16(v);
    l = __float2bfloat16(v - __bfloat162float(h));
}
__device__ __forceinline__ void packsplit2(float a, float b, uint32_t& ph, uint32_t& pl) {
    __nv_bfloat16 ha = __float2bfloat16(a), hb = __float2bfloat16(b);
    __nv_bfloat16 la = __float2bfloat16(a - __bfloat162float(ha));
    __nv_bfloat16 lb = __float2bfloat16(b - __bfloat162float(hb));
    __nv_bfloat162 th = __halves2bfloat162(ha, hb);
    __nv_bfloat162 tl = __halves2bfloat162(la, lb);
    ph = *(uint32_t*)&th;
    pl = *(uint32_t*)&tl;
}
__device__ __forceinline__ uint32_t soff(int row, int ch) {   // GEMM: 64B rows
    return (uint32_t)(row * 64 + ((ch ^ ((row >> 1) & 3)) << 4));
}
__device__ __forceinline__ uint32_t swz(int row, int ch) {    // attn: 128B rows
    return (uint32_t)(row * 128 + ((ch ^ (row & 7)) << 4));
}

// ---------------------------------------------------------------------------
// Weight prep: W[L][K][N] fp32 -> bf16 hi/lo, tile-major blocks of 128n x 32k.
// ---------------------------------------------------------------------------
__global__ void prep_w_kernel(const float* __restrict__ W, __nv_bfloat16* __restrict__ hi,
                              __nv_bfloat16* __restrict__ lo, int K, int N) {
    size_t total = (size_t)kL * K * N;
    int kcnt = K / 32;
    for (size_t idx = (size_t)blockIdx.x * blockDim.x + threadIdx.x; idx < total;
         idx += (size_t)gridDim.x * blockDim.x) {
        size_t per = (size_t)K * N;
        int l = (int)(idx / per);
        int rem = (int)(idx - (size_t)l * per);
        int k = rem / N, n = rem - k * N;
        float v = W[idx];
        __nv_bfloat16 h, lw;
        bsplit(v, h, lw);
        int nt = n >> 7, nl = n & 127, kc = k >> 5, kk = k & 31;
        size_t dst = (size_t)l * per + ((size_t)(nt * kcnt + kc)) * 4096 + nl * 32 + kk;
        hi[dst] = h;
        lo[dst] = lw;
    }
}

// ---------------------------------------------------------------------------
// mma_gemm: modes 0=plain fp32, 1=+Res fp32, 2=relu+bf16 split, 3=scale+bf16 split
// ---------------------------------------------------------------------------
__global__ void __launch_bounds__(256, 1)
mma_gemm(const __nv_bfloat16* __restrict__ Ahi, const __nv_bfloat16* __restrict__ Alo,
         const __nv_bfloat16* __restrict__ Bhi, const __nv_bfloat16* __restrict__ Blo,
         const float* __restrict__ bias, const float* __restrict__ Res,
         float* __restrict__ C, __nv_bfloat16* __restrict__ Chi,
         __nv_bfloat16* __restrict__ Clo, int N, int K, int mode, float oscale) {
    extern __shared__ char smem[];
    const uint32_t sb = smem_u32(smem);
    const int tid = threadIdx.x;
    const int lane = tid & 31, wid = tid >> 5;
    const int wm = (wid & 1) * 64, wn = (wid >> 1) * 32;
    const int m0 = blockIdx.y * 128, n0 = blockIdx.x * 128;
    const int iters = K >> 5;
    const size_t btile = (size_t)blockIdx.x * iters * 4096;

    float acc[4][4][4];
    #pragma unroll
    for (int a = 0; a < 4; a++)
        #pragma unroll
        for (int b = 0; b < 4; b++)
            #pragma unroll
            for (int c = 0; c < 4; c++) acc[a][b][c] = 0.0f;

    auto load_stage = [&](int c, int s) {
        const uint32_t st = sb + (uint32_t)s * kStageBytes;
        #pragma unroll
        for (int p = 0; p < 2; p++) {
            int idx = p * 256 + tid;
            int row = idx >> 2, ch = idx & 3;
            uint32_t so = soff(row, ch);
            const __nv_bfloat16* gAh = Ahi + (size_t)(m0 + row) * K + c * 32 + ch * 8;
            const __nv_bfloat16* gAl = Alo + (size_t)(m0 + row) * K + c * 32 + ch * 8;
            size_t boff = btile + (size_t)c * 4096 + row * 32 + ch * 8;
            CP16(st + so, gAh);
            CP16(st + 8192 + so, gAl);
            CP16(st + 16384 + so, Bhi + boff);
            CP16(st + 24576 + so, Blo + boff);
        }
        CP_COMMIT();
    };

    auto compute_stage = [&](int s) {
        const uint32_t base = sb + (uint32_t)s * kStageBytes;
        #pragma unroll
        for (int ks = 0; ks < 2; ks++) {
            const int kc = ks * 2;
            uint32_t ah[4][4], al[4][4], bh[4][2], bl[4][2];
            #pragma unroll
            for (int mf = 0; mf < 4; mf++) {
                int row = wm + mf * 16 + (lane & 15);
                int ch = kc + (lane >> 4);
                uint32_t so = soff(row, ch);
                LDSM4(ah[mf][0], ah[mf][1], ah[mf][2], ah[mf][3], base + so);
                LDSM4(al[mf][0], al[mf][1], al[mf][2], al[mf][3], base + 8192 + so);
            }
            #pragma unroll
            for (int nb = 0; nb < 2; nb++) {
                int row = wn + nb * 16 + (lane & 7) + ((lane >> 4) << 3);
                int ch = kc + ((lane >> 3) & 1);
                uint32_t so = soff(row, ch);
                LDSM4(bh[2 * nb][0], bh[2 * nb][1], bh[2 * nb + 1][0], bh[2 * nb + 1][1],
                      base + 16384 + so);
                LDSM4(bl[2 * nb][0], bl[2 * nb][1], bl[2 * nb + 1][0], bl[2 * nb + 1][1],
                      base + 24576 + so);
            }
            #pragma unroll
            for (int mf = 0; mf < 4; mf++)
                #pragma unroll
                for (int nf = 0; nf < 4; nf++) {
                    MMA_BF16(acc[mf][nf], ah[mf], bh[nf]);
                    MMA_BF16(acc[mf][nf], ah[mf], bl[nf]);
                    MMA_BF16(acc[mf][nf], al[mf], bh[nf]);
                }
        }
    };

    load_stage(0, 0);
    load_stage(1, 1);

    for (int c = 0; c < iters; c++) {
        const int s = c - (c / kNS) * kNS;
        if (c + 2 < iters) {
            int s2 = (c + 2) % kNS;
            load_stage(c + 2, s2);
            CP_WAIT(2);
        } else if (c + 1 < iters) {
            CP_WAIT(1);
        } else {
            CP_WAIT(0);
        }
        __syncthreads();
        compute_stage(s);
        __syncthreads();
    }

    #pragma unroll
    for (int mf = 0; mf < 4; mf++) {
        #pragma unroll
        for (int h = 0; h < 2; h++) {
            const int r = m0 + wm + mf * 16 + (lane >> 2) + h * 8;
            #pragma unroll
            for (int nf = 0; nf < 4; nf++) {
                const int cc = n0 + wn + nf * 8 + (lane & 3) * 2;
                float v0 = acc[mf][nf][h * 2 + 0] + bias[cc];
                float v1 = acc[mf][nf][h * 2 + 1] + bias[cc + 1];
                size_t base = (size_t)r * N + cc;
                if (mode >= 2) {
                    if (mode == 2) {
                        v0 = fmaxf(v0, 0.0f);
                        v1 = fmaxf(v1, 0.0f);
                    } else {
                        v0 *= oscale;
                        v1 *= oscale;
                    }
                    uint32_t ph, pl;
                    packsplit2(v0, v1, ph, pl);
                    *(uint32_t*)(Chi + base) = ph;
                    *(uint32_t*)(Clo + base) = pl;
                } else if (mode == 1) {
                    float2 rr = *(const float2*)(Res + base);
                    float2 o;
                    o.x = v0 + rr.x;
                    o.y = v1 + rr.y;
                    *(float2*)(C + base) = o;
                } else {
                    float2 o;
                    o.x = v0;
                    o.y = v1;
                    *(float2*)(C + base) = o;
                }
            }
        }
    }
}

// ---------------------------------------------------------------------------
// attn_mma: flash attention on mma.m16n8k16 bf16 (3-term split everywhere).
// Block: 128 q-rows x (head, batch). 8 warps, warp = 16 q-rows (full rows).
// Q pre-scaled by 0.125 in the Q-GEMM epilogue.
// smem: Qh 16K | Ql 16K | 2 stages x (Kh 8K|Kl 8K|Vh 8K|Vl 8K) | pad 512B
// ---------------------------------------------------------------------------
__global__ void __launch_bounds__(256, 1)
attn_mma(const __nv_bfloat16* __restrict__ qh_g, const __nv_bfloat16* __restrict__ ql_g,
         const __nv_bfloat16* __restrict__ kh_g, const __nv_bfloat16* __restrict__ kl_g,
         const __nv_bfloat16* __restrict__ vh_g, const __nv_bfloat16* __restrict__ vl_g,
         const int* __restrict__ xtok, const int* __restrict__ ltp,
         __nv_bfloat16* __restrict__ ohi, __nv_bfloat16* __restrict__ olo) {
    extern __shared__ char smem[];
    const uint32_t sb = smem_u32(smem);
    const int tid = threadIdx.x, lane = tid & 31, w = tid >> 5;
    const int qt = blockIdx.x, hh = blockIdx.y, b = blockIdx.z;
    const int lt = ltp[0];

    const uint32_t QH = sb, QL = sb + 16384;
    const uint32_t STG = sb + 32768;      // + s*32768: Kh, Kl, Vh, Vl (8K each)
    char* padp = smem + 98304;

    // pad mask (512 keys of this batch)
    #pragma unroll
    for (int i = 0; i < 2; i++)
        padp[tid + i * 256] = (xtok[b * kS + tid + i * 256] > 0) ? 1 : 0;

    // Q tile loads (group 0)
    const size_t qgbase = ((size_t)(b * kS + qt * 128)) * kD + hh * 64;
    #pragma unroll
    for (int i = 0; i < 4; i++) {
        int idx = i * 256 + tid;            // 0..1023
        int row = idx >> 3, ch = idx & 7;
        uint32_t so = swz(row, ch);
        size_t go = qgbase + (size_t)row * kD + ch * 8;
        CP16(QH + so, qh_g + go);
        CP16(QL + so, ql_g + go);
    }
    CP_COMMIT();

    auto load_kv = [&](int kt, int s) {
        const uint32_t st = STG + (uint32_t)s * 32768;
        const size_t gb = ((size_t)(b * kS + kt * 64)) * kD + hh * 64;
        #pragma unroll
        for (int i = 0; i < 2; i++) {
            int idx = i * 256 + tid;
            int row = idx >> 3, ch = idx & 7;
            uint32_t so = swz(row, ch);
            size_t go = gb + (size_t)row * kD + ch * 8;
            CP16(st + so,         kh_g + go);
            CP16(st + 8192 + so,  kl_g + go);
            CP16(st + 16384 + so, vh_g + go);
            CP16(st + 24576 + so, vl_g + go);
        }
        CP_COMMIT();
    };

    load_kv(0, 0);
    load_kv(1, 1);

    uint32_t qfh[4][4], qfl[4][4];
    float oacc[8][4];
    #pragma unroll
    for (int i = 0; i < 8; i++)
        #pragma unroll
        for (int j = 0; j < 4; j++) oacc[i][j] = 0.0f;
    float m_[2] = {-INFINITY, -INFINITY}, l_[2] = {0.0f, 0.0f};

    const int rbase = qt * 128 + w * 16 + (lane >> 2);     // row0; row1 = +8

    for (int kt = 0; kt < 8; kt++) {
        if (kt < 7) { CP_WAIT(1); } else { CP_WAIT(0); }
        __syncthreads();

        if (kt == 0) {
            #pragma unroll
            for (int ks = 0; ks < 4; ks++) {
                int row = w * 16 + (lane & 15);
                int ch = ks * 2 + (lane >> 4);
                uint32_t so = swz(row, ch);
                LDSM4(qfh[ks][0], qfh[ks][1], qfh[ks][2], qfh[ks][3], QH + so);
                LDSM4(qfl[ks][0], qfl[ks][1], qfl[ks][2], qfl[ks][3], QL + so);
            }
        }

        const uint32_t st = STG + (uint32_t)(kt & 1) * 32768;
        const uint32_t KHs = st, KLs = st + 8192, VHs = st + 16384, VLs = st + 24576;

        // ---- S = Q K^T (keys = n, dh = k) ----
        float s4[8][4];
        #pragma unroll
        for (int i = 0; i < 8; i++)
            #pragma unroll
            for (int j = 0; j < 4; j++) s4[i][j] = 0.0f;

        #pragma unroll
        for (int ks = 0; ks < 4; ks++) {
            uint32_t bh[8][2], bl[8][2];
            #pragma unroll
            for (int kg = 0; kg < 4; kg++) {
                int row = kg * 16 + (lane & 7) + ((lane >> 4) << 3);
                int ch = ks * 2 + ((lane >> 3) & 1);
                uint32_t so = swz(row, ch);
                LDSM4(bh[2 * kg][0], bh[2 * kg][1], bh[2 * kg + 1][0], bh[2 * kg + 1][1],
                      KHs + so);
                LDSM4(bl[2 * kg][0], bl[2 * kg][1], bl[2 * kg + 1][0], bl[2 * kg + 1][1],
                      KLs + so);
            }
            #pragma unroll
            for (int nf = 0; nf < 8; nf++) {
                MMA_BF16(s4[nf], qfh[ks], bh[nf]);
                MMA_BF16(s4[nf], qfh[ks], bl[nf]);
                MMA_BF16(s4[nf], qfl[ks], bh[nf]);
            }
        }

        // ---- mask ----
        #pragma unroll
        for (int nf = 0; nf < 8; nf++) {
            int col = kt * 64 + nf * 8 + (lane & 3) * 2;
            bool p0 = padp[col] != 0;
            bool p1 = padp[col + 1] != 0;
            bool c0lt = col < lt, c1lt = (col + 1) < lt;
            s4[nf][0] = (p0 && (col <= rbase || c0lt))         ? s4[nf][0] : -1.0e9f;
            s4[nf][1] = (p1 && (col + 1 <= rbase || c1lt))     ? s4[nf][1] : -1.0e9f;
            s4[nf][2] = (p0 && (col <= rbase + 8 || c0lt))     ? s4[nf][2] : -1.0e9f;
            s4[nf][3] = (p1 && (col + 1 <= rbase + 8 || c1lt)) ? s4[nf][3] : -1.0e9f;
        }

        // ---- online softmax (rows r0, r1 per thread; 4-lane groups) ----
        #pragma unroll
        for (int r = 0; r < 2; r++) {
            float tm = -INFINITY;
            #pragma unroll
            for (int nf = 0; nf < 8; nf++)
                tm = fmaxf(tm, fmaxf(s4[nf][2 * r], s4[nf][2 * r + 1]));
            tm = fmaxf(tm, __shfl_xor_sync(0xffffffffu, tm, 1));
            tm = fmaxf(tm, __shfl_xor_sync(0xffffffffu, tm, 2));
            float nm = fmaxf(m_[r], tm);
            float al = __expf(m_[r] - nm);
            m_[r] = nm;
            float ts = 0.0f;
            #pragma unroll
            for (int nf = 0; nf < 8; nf++) {
                float p0 = __expf(s4[nf][2 * r] - nm);
                float p1 = __expf(s4[nf][2 * r + 1] - nm);
                s4[nf][2 * r] = p0;
                s4[nf][2 * r + 1] = p1;
                ts += p0 + p1;
            }
            ts += __shfl_xor_sync(0xffffffffu, ts, 1);
            ts += __shfl_xor_sync(0xffffffffu, ts, 2);
            l_[r] = l_[r] * al + ts;
            #pragma unroll
            for (int nf = 0; nf < 8; nf++) {
                oacc[nf][2 * r] *= al;
                oacc[nf][2 * r + 1] *= al;
            }
        }

        // ---- O += P V (keys = k, dh = n) ----
        #pragma unroll
        for (int kv = 0; kv < 4; kv++) {
            uint32_t pah[4], pal[4];
            packsplit2(s4[2 * kv][0], s4[2 * kv][1], pah[0], pal[0]);
            packsplit2(s4[2 * kv][2], s4[2 * kv][3], pah[1], pal[1]);
            packsplit2(s4[2 * kv + 1][0], s4[2 * kv + 1][1], pah[2], pal[2]);
            packsplit2(s4[2 * kv + 1][2], s4[2 * kv + 1][3], pah[3], pal[3]);
            #pragma unroll
            for (int dg = 0; dg < 4; dg++) {
                int row = kv * 16 + (lane & 7) + ((lane >> 3) & 1) * 8;
                int ch = dg * 2 + (lane >> 4);
                uint32_t so = swz(row, ch);
                uint32_t vh0, vh1, vh2, vh3, vl0, vl1, vl2, vl3;
                LDSM4T(vh0, vh1, vh2, vh3, VHs + so);
                LDSM4T(vl0, vl1, vl2, vl3, VLs + so);
                uint32_t bfh0[2] = {vh0, vh1}, bfh1[2] = {vh2, vh3};
                uint32_t bfl0[2] = {vl0, vl1}, bfl1[2] = {vl2, vl3};
                MMA_BF16(oacc[dg * 2], pah, bfh0);
                MMA_BF16(oacc[dg * 2], pah, bfl0);
                MMA_BF16(oacc[dg * 2], pal, bfh0);
                MMA_BF16(oacc[dg * 2 + 1], pah, bfh1);
                MMA_BF16(oacc[dg * 2 + 1], pah, bfl1);
                MMA_BF16(oacc[dg * 2 + 1], pal, bfh1);
            }
        }

        __syncthreads();
        if (kt + 2 < 8) load_kv(kt + 2, kt & 1);
    }

    // ---- epilogue: normalize + bf16 split write ----
    float inv0 = 1.0f / l_[0], inv1 = 1.0f / l_[1];
    const int row0 = qt * 128 + w * 16 + (lane >> 2);
    #pragma unroll
    for (int nf = 0; nf < 8; nf++) {
        int col = hh * 64 + nf * 8 + (lane & 3) * 2;
        size_t b0 = ((size_t)(b * kS + row0)) * kD + col;
        size_t b1 = ((size_t)(b * kS + row0 + 8)) * kD + col;
        uint32_t ph, pl;
        packsplit2(oacc[nf][0] * inv0, oacc[nf][1] * inv0, ph, pl);
        *(uint32_t*)(ohi + b0) = ph;
        *(uint32_t*)(olo + b0) = pl;
        packsplit2(oacc[nf][2] * inv1, oacc[nf][3] * inv1, ph, pl);
        *(uint32_t*)(ohi + b1) = ph;
        *(uint32_t*)(olo + b1) = pl;
    }
}

// ---------------------------------------------------------------------------
__global__ void pe_kernel(float* __restrict__ pe) {
    int idx = blockIdx.x * blockDim.x + threadIdx.x;
    if (idx >= kS * kD) return;
    int s = idx / kD;
    int j = idx - s * kD;
    int i2 = j & ~1;
    double ang = (double)s * pow(10000.0, -(double)i2 / (double)kD);
    pe[idx] = (j & 1) ? (float)cos(ang) : (float)sin(ang);
}

__global__ void embed_kernel(const int* __restrict__ x, const int* __restrict__ tim,
                             const float* __restrict__ tok_emb,
                             const float* __restrict__ time_emb,
                             const float* __restrict__ pe, float* __restrict__ out) {
    int idx = blockIdx.x * blockDim.x + threadIdx.x;
    if (idx >= kM * kD) return;
    int bs = idx / kD;
    int j = idx - bs * kD;
    int s = bs & (kS - 1);
    out[idx] = tok_emb[(size_t)x[bs] * kD + j] + time_emb[(size_t)tim[bs] * kD + j]
             + pe[s * kD + j];
}

// ----------------------------- LayerNorm ------------------------------------
__device__ __forceinline__ float block_reduce_sum(float v, float* sred) {
    #pragma unroll
    for (int o = 16; o > 0; o >>= 1) v += __shfl_xor_sync(0xffffffffu, v, o);
    int w = threadIdx.x >> 5;
    __syncthreads();
    if ((threadIdx.x & 31) == 0) sred[w] = v;
    __syncthreads();
    if (threadIdx.x == 0) {
        float t = sred[0];
        #pragma unroll
        for (int i = 1; i < 8; i++) t += sred[i];
        sred[0] = t;
    }
    __syncthreads();
    return sred[0];
}

__global__ void ln_kernel(const float* __restrict__ in, float* __restrict__ out,
                          const float* __restrict__ g, const float* __restrict__ b) {
    __shared__ float sred[8];
    int row = blockIdx.x, tid = threadIdx.x;
    const float* ip = in + (size_t)row * kD;
    float v0 = ip[tid], v1 = ip[tid + 256], v2 = ip[tid + 512];
    float sum = block_reduce_sum(v0 + v1 + v2, sred);
    float mu = sum * (1.0f / 768.0f);
    float d0 = v0 - mu, d1 = v1 - mu, d2 = v2 - mu;
    float sq = block_reduce_sum(d0 * d0 + d1 * d1 + d2 * d2, sred);
    float inv = 1.0f / sqrtf(sq * (1.0f / 768.0f) + 1e-6f);
    float* op = out + (size_t)row * kD;
    op[tid]       = g[tid]       * d0 * inv + b[tid];
    op[tid + 256] = g[tid + 256] * d1 * inv + b[tid + 256];
    op[tid + 512] = g[tid + 512] * d2 * inv + b[tid + 512];
}

__global__ void ln_split_kernel(const float* __restrict__ in,
                                __nv_bfloat16* __restrict__ ohi,
                                __nv_bfloat16* __restrict__ olo,
                                const float* __restrict__ g, const float* __restrict__ b) {
    __shared__ float sred[8];
    int row = blockIdx.x, tid = threadIdx.x;
    const float* ip = in + (size_t)row * kD;
    float v0 = ip[tid], v1 = ip[tid + 256], v2 = ip[tid + 512];
    float sum = block_reduce_sum(v0 + v1 + v2, sred);
    float mu = sum * (1.0f / 768.0f);
    float d0 = v0 - mu, d1 = v1 - mu, d2 = v2 - mu;
    float sq = block_reduce_sum(d0 * d0 + d1 * d1 + d2 * d2, sred);
    float inv = 1.0f / sqrtf(sq * (1.0f / 768.0f) + 1e-6f);
    size_t base = (size_t)row * kD;
    float r0 = g[tid] * d0 * inv + b[tid];
    float r1 = g[tid + 256] * d1 * inv + b[tid + 256];
    float r2 = g[tid + 512] * d2 * inv + b[tid + 512];
    __nv_bfloat16 h, l;
    bsplit(r0, h, l); ohi[base + tid]       = h; olo[base + tid]       = l;
    bsplit(r1, h, l); ohi[base + tid + 256] = h; olo[base + tid + 256] = l;
    bsplit(r2, h, l); ohi[base + tid + 512] = h; olo[base + tid + 512] = l;
}

__global__ void copy_kernel(const float* __restrict__ in, float* __restrict__ out) {
    int idx = blockIdx.x * blockDim.x + threadIdx.x;
    if (idx >= kM * kD / 4) return;
    ((float4*)out)[idx] = ((const float4*)in)[idx];
}

// ---------------------------------------------------------------------------
extern "C" void kernel_launch(void* const* d_in, const int* in_sizes, int n_in,
                              void* d_out, int out_size) {
    const int*   x        = (const int*)d_in[0];
    const int*   tim      = (const int*)d_in[1];
    const int*   len_traj = (const int*)d_in[2];
    const float* tok_emb  = (const float*)d_in[3];
    const float* time_emb = (const float*)d_in[4];
    const float* emb_g    = (const float*)d_in[5];
    const float* emb_b    = (const float*)d_in[6];
    const float* Wq = (const float*)d_in[7];
    const float* bq = (const float*)d_in[8];
    const float* Wk = (const float*)d_in[9];
    const float* bk = (const float*)d_in[10];
    const float* Wv = (const float*)d_in[11];
    const float* bv = (const float*)d_in[12];
    const float* Wo = (const float*)d_in[13];
    const float* bo = (const float*)d_in[14];
    const float* ln1_g = (const float*)d_in[15];
    const float* ln1_b = (const float*)d_in[16];
    const float* W1 = (const float*)d_in[17];
    const float* b1 = (const float*)d_in[18];
    const float* W2 = (const float*)d_in[19];
    const float* b2 = (const float*)d_in[20];
    const float* ln2_g = (const float*)d_in[21];
    const float* ln2_b = (const float*)d_in[22];
    float* out = (float*)d_out;

    float *ph, *ptmp, *ppe;
    __nv_bfloat16 *phnh, *phnl, *pqh, *pql, *pkh, *pkl, *pvh, *pvl;
    __nv_bfloat16 *pohi, *polo, *pffh, *pffl;
    __nv_bfloat16 *wqh, *wql, *wkh, *wkl, *wvh, *wvl, *woh, *wol, *w1h, *w1l, *w2h, *w2l;
    cudaGetSymbolAddress((void**)&ph,   g_h);
    cudaGetSymbolAddress((void**)&ptmp, g_tmp);
    cudaGetSymbolAddress((void**)&ppe,  g_pe);
    cudaGetSymbolAddress((void**)&phnh, g_hn_hi);
    cudaGetSymbolAddress((void**)&phnl, g_hn_lo);
    cudaGetSymbolAddress((void**)&pqh,  g_q_hi);
    cudaGetSymbolAddress((void**)&pql,  g_q_lo);
    cudaGetSymbolAddress((void**)&pkh,  g_k_hi);
    cudaGetSymbolAddress((void**)&pkl,  g_k_lo);
    cudaGetSymbolAddress((void**)&pvh,  g_v_hi);
    cudaGetSymbolAddress((void**)&pvl,  g_v_lo);
    cudaGetSymbolAddress((void**)&pohi, g_o_hi);
    cudaGetSymbolAddress((void**)&polo, g_o_lo);
    cudaGetSymbolAddress((void**)&pffh, g_ff_hi);
    cudaGetSymbolAddress((void**)&pffl, g_ff_lo);
    cudaGetSymbolAddress((void**)&wqh, g_wq_hi);
    cudaGetSymbolAddress((void**)&wql, g_wq_lo);
    cudaGetSymbolAddress((void**)&wkh, g_wk_hi);
    cudaGetSymbolAddress((void**)&wkl, g_wk_lo);
    cudaGetSymbolAddress((void**)&wvh, g_wv_hi);
    cudaGetSymbolAddress((void**)&wvl, g_wv_lo);
    cudaGetSymbolAddress((void**)&woh, g_wo_hi);
    cudaGetSymbolAddress((void**)&wol, g_wo_lo);
    cudaGetSymbolAddress((void**)&w1h, g_w1_hi);
    cudaGetSymbolAddress((void**)&w1l, g_w1_lo);
    cudaGetSymbolAddress((void**)&w2h, g_w2_hi);
    cudaGetSymbolAddress((void**)&w2l, g_w2_lo);

    cudaFuncSetAttribute(mma_gemm, cudaFuncAttributeMaxDynamicSharedMemorySize, kSmemBytes);
    cudaFuncSetAttribute(attn_mma, cudaFuncAttributeMaxDynamicSharedMemorySize, kAttnSmem);

    prep_w_kernel<<<4096, 256>>>(Wq, wqh, wql, kD, kD);
    prep_w_kernel<<<4096, 256>>>(Wk, wkh, wkl, kD, kD);
    prep_w_kernel<<<4096, 256>>>(Wv, wvh, wvl, kD, kD);
    prep_w_kernel<<<4096, 256>>>(Wo, woh, wol, kD, kD);
    prep_w_kernel<<<8192, 256>>>(W1, w1h, w1l, kD, kFF);
    prep_w_kernel<<<8192, 256>>>(W2, w2h, w2l, kFF, kD);

    pe_kernel<<<(kS * kD + 255) / 256, 256>>>(ppe);
    embed_kernel<<<(kM * kD + 255) / 256, 256>>>(x, tim, tok_emb, time_emb, ppe, ptmp);
    ln_kernel<<<kM, 256>>>(ptmp, ph, emb_g, emb_b);

    const dim3 gProj(kD / 128, kM / 128);
    const dim3 gFF1(kFF / 128, kM / 128);
    const dim3 gAttn(kS / 128, kH, kB);

    for (int i = 0; i < kL; i++) {
        const size_t wD = (size_t)i * kD * kD;
        const size_t wF = (size_t)i * kD * kFF;
        ln_split_kernel<<<kM, 256>>>(ph, phnh, phnl, ln1_g + i * kD, ln1_b + i * kD);
        mma_gemm<<<gProj, 256, kSmemBytes>>>(phnh, phnl, wqh + wD, wql + wD, bq + i * kD,
                                             nullptr, nullptr, pqh, pql, kD, kD, 3, 0.125f);
        mma_gemm<<<gProj, 256, kSmemBytes>>>(phnh, phnl, wkh + wD, wkl + wD, bk + i * kD,
                                             nullptr, nullptr, pkh, pkl, kD, kD, 3, 1.0f);
        mma_gemm<<<gProj, 256, kSmemBytes>>>(phnh, phnl, wvh + wD, wvl + wD, bv + i * kD,
                                             nullptr, nullptr, pvh, pvl, kD, kD, 3, 1.0f);
        attn_mma<<<gAttn, 256, kAttnSmem>>>(pqh, pql, pkh, pkl, pvh, pvl, x, len_traj,
                                            pohi, polo);
        mma_gemm<<<gProj, 256, kSmemBytes>>>(pohi, polo, woh + wD, wol + wD, bo + i * kD,
                                             ph, ph, nullptr, nullptr, kD, kD, 1, 1.0f);
        ln_split_kernel<<<kM, 256>>>(ph, phnh, phnl, ln2_g + i * kD, ln2_b + i * kD);
        mma_gemm<<<gFF1, 256, kSmemBytes>>>(phnh, phnl, w1h + wF, w1l + wF, b1 + i * kFF,
                                            nullptr, nullptr, pffh, pffl, kFF, kD, 2, 1.0f);
        mma_gemm<<<gProj, 256, kSmemBytes>>>(pffh, pffl, w2h + wF, w2l + wF, b2 + i * kD,
                                             ph, ph, nullptr, nullptr, kD, kFF, 1, 1.0f);
    }

    copy_kernel<<<(kM * kD / 4 + 255) / 256, 256>>>(ph, out);
}

// round 6
// speedup vs baseline: 3.6964x; 1.3544x over previous
#include <cuda_runtime.h>
#include <cuda_fp16.h>
#include <math.h>
#include <stdint.h>

// ---------------------------------------------------------------------------
// Bert_Traj_Model: B=32, S=512, D=768, H=12, dh=64, FF=3072, L=12, fp32 I/O.
// Round 5: fp16 2-product GEMMs (A split hi/lo, W single fp16), fused QKV
// GEMM (scale folded into Wq), attention PV 2-product, 2 CTA/SM GEMM.
// ---------------------------------------------------------------------------

namespace {
constexpr int kB  = 32;
constexpr int kS  = 512;
constexpr int kD  = 768;
constexpr int kH  = 12;
constexpr int kFF = 3072;
constexpr int kL  = 12;
constexpr int kM  = kB * kS;               // 16384 rows
constexpr int kQKV = 3 * kD;               // 2304
constexpr int kStageBytes = 24576;         // Ahi 8K, Alo 8K, B 8K
constexpr int kNS = 3;
constexpr int kSmemBytes = kNS * kStageBytes;   // 72KB
constexpr int kAttnSmem = 32768 + 2 * 24576 + 512;  // 82432
}

// ----------------------------- scratch (no allocs allowed) ------------------
__device__ float g_h  [(size_t)kM * kD];
__device__ float g_tmp[(size_t)kM * kD];
__device__ float g_bqkv[kL * kQKV];
__device__ __half g_hn_hi [(size_t)kM * kD];
__device__ __half g_hn_lo [(size_t)kM * kD];
__device__ __half g_qkv_hi[(size_t)kM * kQKV];
__device__ __half g_qkv_lo[(size_t)kM * kQKV];
__device__ __half g_o_hi  [(size_t)kM * kD];
__device__ __half g_o_lo  [(size_t)kM * kD];
__device__ __half g_ff_hi [(size_t)kM * kFF];
__device__ __half g_ff_lo [(size_t)kM * kFF];
// pre-tiled fp16 weights: blocks of 128(n) x 32(k), row-major in block
__device__ __half g_wqkv[(size_t)kL * kD * kQKV];
__device__ __half g_wo  [(size_t)kL * kD * kD];
__device__ __half g_w1  [(size_t)kL * kD * kFF];
__device__ __half g_w2  [(size_t)kL * kFF * kD];

// ----------------------------- PTX helpers ---------------------------------
__device__ __forceinline__ uint32_t smem_u32(const void* p) {
    uint32_t a;
    asm("{ .reg .u64 t; cvta.to.shared.u64 t, %1; cvt.u32.u64 %0, t; }" : "=r"(a) : "l"(p));
    return a;
}
#define CP16(dst, src) asm volatile("cp.async.cg.shared.global [%0], [%1], 16;" :: "r"(dst), "l"(src))
#define CP_COMMIT()    asm volatile("cp.async.commit_group;" ::: "memory")
#define CP_WAIT(n)     asm volatile("cp.async.wait_group %0;" :: "n"(n) : "memory")

#define LDSM4(r0, r1, r2, r3, a)                                                \
    asm volatile("ldmatrix.sync.aligned.m8n8.x4.shared.b16 {%0,%1,%2,%3}, [%4];" \
                 : "=r"(r0), "=r"(r1), "=r"(r2), "=r"(r3) : "r"(a))
#define LDSM4T(r0, r1, r2, r3, a)                                               \
    asm volatile("ldmatrix.sync.aligned.m8n8.x4.trans.shared.b16 {%0,%1,%2,%3}, [%4];" \
                 : "=r"(r0), "=r"(r1), "=r"(r2), "=r"(r3) : "r"(a))
#define MMA_F16(d, a, b)                                                        \
    asm volatile("mma.sync.aligned.m16n8k16.row.col.f32.f16.f16.f32 "           \
                 "{%0,%1,%2,%3}, {%4,%5,%6,%7}, {%8,%9}, {%0,%1,%2,%3};"        \
                 : "+f"((d)[0]), "+f"((d)[1]), "+f"((d)[2]), "+f"((d)[3])       \
                 : "r"((a)[0]), "r"((a)[1]), "r"((a)[2]), "r"((a)[3]),          \
                   "r"((b)[0]), "r"((b)[1]))

__device__ __forceinline__ void hsplit(float v, __half& h, __half& l) {
    h = __float2half_rn(v);
    l = __float2half_rn(v - __half2float(h));
}
__device__ __forceinline__ void packsplit2h(float a, float b, uint32_t& ph, uint32_t& pl) {
    __half ha = __float2half_rn(a), hb = __float2half_rn(b);
    __half la = __float2half_rn(a - __half2float(ha));
    __half lb = __float2half_rn(b - __half2float(hb));
    __half2 th = __halves2half2(ha, hb), tl = __halves2half2(la, lb);
    ph = *(uint32_t*)&th;
    pl = *(uint32_t*)&tl;
}
__device__ __forceinline__ uint32_t soff(int row, int ch) {   // 64B rows
    return (uint32_t)(row * 64 + ((ch ^ ((row >> 1) & 3)) << 4));
}
__device__ __forceinline__ uint32_t swz(int row, int ch) {    // 128B rows
    return (uint32_t)(row * 128 + ((ch ^ (row & 7)) << 4));
}

// ---------------------------------------------------------------------------
// Weight prep: W[L][K][Nsrc] fp32 -> fp16 tiles of 128n x 32k at nt offset.
// ---------------------------------------------------------------------------
__global__ void prep_w_off(const float* __restrict__ W, __half* __restrict__ dst,
                           int K, int Nsrc, int Ntot, int ntoff, float scale) {
    size_t total = (size_t)kL * K * Nsrc;
    int kcnt = K / 32;
    size_t per_dst = (size_t)K * Ntot;
    for (size_t idx = (size_t)blockIdx.x * blockDim.x + threadIdx.x; idx < total;
         idx += (size_t)gridDim.x * blockDim.x) {
        size_t per = (size_t)K * Nsrc;
        int l = (int)(idx / per);
        int rem = (int)(idx - (size_t)l * per);
        int k = rem / Nsrc, n = rem - k * Nsrc;
        float v = W[idx] * scale;
        int ntg = ntoff + (n >> 7);
        size_t d = (size_t)l * per_dst + ((size_t)(ntg * kcnt + (k >> 5))) * 4096
                 + (n & 127) * 32 + (k & 31);
        dst[d] = __float2half_rn(v);
    }
}

__global__ void bias_qkv_kernel(const float* __restrict__ bq, const float* __restrict__ bk,
                                const float* __restrict__ bv, float* __restrict__ dst) {
    int idx = blockIdx.x * blockDim.x + threadIdx.x;
    if (idx >= kL * kQKV) return;
    int l = idx / kQKV, j = idx - l * kQKV;
    float v;
    if (j < kD)            v = 0.125f * bq[l * kD + j];
    else if (j < 2 * kD)   v = bk[l * kD + j - kD];
    else                   v = bv[l * kD + j - 2 * kD];
    dst[idx] = v;
}

// ---------------------------------------------------------------------------
// mma_gemm: C[M,N] = epi(A @ W + bias). A hi/lo fp16, W single fp16 tiles.
// modes: 1=+Res fp32 out, 2=relu+fp16 split, 3=fp16 split.
// 128x128 CTA tile, 8 warps of 32x64, 3-stage cp.async, 2 CTA/SM.
// ---------------------------------------------------------------------------
__global__ void __launch_bounds__(256, 2)
mma_gemm(const __half* __restrict__ Ahi, const __half* __restrict__ Alo,
         const __half* __restrict__ Bw, const float* __restrict__ bias,
         const float* __restrict__ Res, float* __restrict__ C,
         __half* __restrict__ Chi, __half* __restrict__ Clo, int N, int K, int mode) {
    extern __shared__ char smem[];
    const uint32_t sb = smem_u32(smem);
    const int tid = threadIdx.x;
    const int lane = tid & 31, wid = tid >> 5;
    const int wm = (wid & 3) * 32, wn = (wid >> 2) * 64;
    const int m0 = blockIdx.y * 128, n0 = blockIdx.x * 128;
    const int iters = K >> 5;
    const size_t btile = (size_t)blockIdx.x * iters * 4096;

    float acc[2][8][4];
    #pragma unroll
    for (int a = 0; a < 2; a++)
        #pragma unroll
        for (int b = 0; b < 8; b++)
            #pragma unroll
            for (int c = 0; c < 4; c++) acc[a][b][c] = 0.0f;

    auto load_stage = [&](int c, int s) {
        const uint32_t st = sb + (uint32_t)s * kStageBytes;
        #pragma unroll
        for (int p = 0; p < 2; p++) {
            int idx = p * 256 + tid;
            int row = idx >> 2, ch = idx & 3;
            uint32_t so = soff(row, ch);
            const __half* gAh = Ahi + (size_t)(m0 + row) * K + c * 32 + ch * 8;
            const __half* gAl = Alo + (size_t)(m0 + row) * K + c * 32 + ch * 8;
            size_t boff = btile + (size_t)c * 4096 + row * 32 + ch * 8;
            CP16(st + so, gAh);
            CP16(st + 8192 + so, gAl);
            CP16(st + 16384 + so, Bw + boff);
        }
        CP_COMMIT();
    };

    auto compute_stage = [&](int s) {
        const uint32_t base = sb + (uint32_t)s * kStageBytes;
        #pragma unroll
        for (int ks = 0; ks < 2; ks++) {
            const int kc = ks * 2;
            uint32_t ah[2][4], al[2][4], bh[8][2];
            #pragma unroll
            for (int mf = 0; mf < 2; mf++) {
                int row = wm + mf * 16 + (lane & 15);
                int ch = kc + (lane >> 4);
                uint32_t so = soff(row, ch);
                LDSM4(ah[mf][0], ah[mf][1], ah[mf][2], ah[mf][3], base + so);
                LDSM4(al[mf][0], al[mf][1], al[mf][2], al[mf][3], base + 8192 + so);
            }
            #pragma unroll
            for (int nb = 0; nb < 4; nb++) {
                int row = wn + nb * 16 + (lane & 7) + ((lane >> 4) << 3);
                int ch = kc + ((lane >> 3) & 1);
                uint32_t so = soff(row, ch);
                LDSM4(bh[2 * nb][0], bh[2 * nb][1], bh[2 * nb + 1][0], bh[2 * nb + 1][1],
                      base + 16384 + so);
            }
            #pragma unroll
            for (int mf = 0; mf < 2; mf++)
                #pragma unroll
                for (int nf = 0; nf < 8; nf++) {
                    MMA_F16(acc[mf][nf], ah[mf], bh[nf]);
                    MMA_F16(acc[mf][nf], al[mf], bh[nf]);
                }
        }
    };

    load_stage(0, 0);
    load_stage(1, 1);

    for (int c = 0; c < iters; c++) {
        const int s = c - (c / kNS) * kNS;
        if (c + 2 < iters) {
            int s2 = (c + 2) % kNS;
            load_stage(c + 2, s2);
            CP_WAIT(2);
        } else if (c + 1 < iters) {
            CP_WAIT(1);
        } else {
            CP_WAIT(0);
        }
        __syncthreads();
        compute_stage(s);
        __syncthreads();
    }

    #pragma unroll
    for (int mf = 0; mf < 2; mf++) {
        #pragma unroll
        for (int h = 0; h < 2; h++) {
            const int r = m0 + wm + mf * 16 + (lane >> 2) + h * 8;
            #pragma unroll
            for (int nf = 0; nf < 8; nf++) {
                const int cc = n0 + wn + nf * 8 + (lane & 3) * 2;
                float v0 = acc[mf][nf][h * 2 + 0] + bias[cc];
                float v1 = acc[mf][nf][h * 2 + 1] + bias[cc + 1];
                size_t base = (size_t)r * N + cc;
                if (mode >= 2) {
                    if (mode == 2) {
                        v0 = fmaxf(v0, 0.0f);
                        v1 = fmaxf(v1, 0.0f);
                    }
                    uint32_t ph, pl;
                    packsplit2h(v0, v1, ph, pl);
                    *(uint32_t*)(Chi + base) = ph;
                    *(uint32_t*)(Clo + base) = pl;
                } else {
                    float2 rr = *(const float2*)(Res + base);
                    float2 o;
                    o.x = v0 + rr.x;
                    o.y = v1 + rr.y;
                    *(float2*)(C + base) = o;
                }
            }
        }
    }
}

// ---------------------------------------------------------------------------
// attn_mma: flash attention. QK 3-product (q,k split), PV 2-product (P split,
// V single). Q pre-scaled via folded weights. Block: 128 q-rows x (head,batch).
// smem: Qh 16K | Ql 16K | 2 stages x (Kh 8K|Kl 8K|Vh 8K) | pad 512
// ---------------------------------------------------------------------------
__global__ void __launch_bounds__(256, 1)
attn_mma(const __half* __restrict__ qh_g, const __half* __restrict__ ql_g,
         const __half* __restrict__ kh_g, const __half* __restrict__ kl_g,
         const __half* __restrict__ vh_g, int rstride,
         const int* __restrict__ xtok, const int* __restrict__ ltp,
         __half* __restrict__ ohi, __half* __restrict__ olo) {
    extern __shared__ char smem[];
    const uint32_t sb = smem_u32(smem);
    const int tid = threadIdx.x, lane = tid & 31, w = tid >> 5;
    const int qt = blockIdx.x, hh = blockIdx.y, b = blockIdx.z;
    const int lt = ltp[0];

    const uint32_t QH = sb, QL = sb + 16384;
    const uint32_t STG = sb + 32768;      // + s*24576: Kh, Kl, Vh (8K each)
    char* padp = smem + 32768 + 2 * 24576;

    #pragma unroll
    for (int i = 0; i < 2; i++)
        padp[tid + i * 256] = (xtok[b * kS + tid + i * 256] > 0) ? 1 : 0;

    const size_t qgbase = ((size_t)(b * kS + qt * 128)) * rstride + hh * 64;
    #pragma unroll
    for (int i = 0; i < 4; i++) {
        int idx = i * 256 + tid;
        int row = idx >> 3, ch = idx & 7;
        uint32_t so = swz(row, ch);
        size_t go = qgbase + (size_t)row * rstride + ch * 8;
        CP16(QH + so, qh_g + go);
        CP16(QL + so, ql_g + go);
    }
    CP_COMMIT();

    auto load_kv = [&](int kt, int s) {
        const uint32_t st = STG + (uint32_t)s * 24576;
        const size_t gb = ((size_t)(b * kS + kt * 64)) * rstride + hh * 64;
        #pragma unroll
        for (int i = 0; i < 2; i++) {
            int idx = i * 256 + tid;
            int row = idx >> 3, ch = idx & 7;
            uint32_t so = swz(row, ch);
            size_t go = gb + (size_t)row * rstride + ch * 8;
            CP16(st + so,         kh_g + go);
            CP16(st + 8192 + so,  kl_g + go);
            CP16(st + 16384 + so, vh_g + go);
        }
        CP_COMMIT();
    };

    load_kv(0, 0);
    load_kv(1, 1);

    uint32_t qfh[4][4], qfl[4][4];
    float oacc[8][4];
    #pragma unroll
    for (int i = 0; i < 8; i++)
        #pragma unroll
        for (int j = 0; j < 4; j++) oacc[i][j] = 0.0f;
    float m_[2] = {-INFINITY, -INFINITY}, l_[2] = {0.0f, 0.0f};

    const int rbase = qt * 128 + w * 16 + (lane >> 2);

    for (int kt = 0; kt < 8; kt++) {
        if (kt < 7) { CP_WAIT(1); } else { CP_WAIT(0); }
        __syncthreads();

        if (kt == 0) {
            #pragma unroll
            for (int ks = 0; ks < 4; ks++) {
                int row = w * 16 + (lane & 15);
                int ch = ks * 2 + (lane >> 4);
                uint32_t so = swz(row, ch);
                LDSM4(qfh[ks][0], qfh[ks][1], qfh[ks][2], qfh[ks][3], QH + so);
                LDSM4(qfl[ks][0], qfl[ks][1], qfl[ks][2], qfl[ks][3], QL + so);
            }
        }

        const uint32_t st = STG + (uint32_t)(kt & 1) * 24576;
        const uint32_t KHs = st, KLs = st + 8192, VHs = st + 16384;

        float s4[8][4];
        #pragma unroll
        for (int i = 0; i < 8; i++)
            #pragma unroll
            for (int j = 0; j < 4; j++) s4[i][j] = 0.0f;

        #pragma unroll
        for (int ks = 0; ks < 4; ks++) {
            uint32_t bh[8][2], bl[8][2];
            #pragma unroll
            for (int kg = 0; kg < 4; kg++) {
                int row = kg * 16 + (lane & 7) + ((lane >> 4) << 3);
                int ch = ks * 2 + ((lane >> 3) & 1);
                uint32_t so = swz(row, ch);
                LDSM4(bh[2 * kg][0], bh[2 * kg][1], bh[2 * kg + 1][0], bh[2 * kg + 1][1],
                      KHs + so);
                LDSM4(bl[2 * kg][0], bl[2 * kg][1], bl[2 * kg + 1][0], bl[2 * kg + 1][1],
                      KLs + so);
            }
            #pragma unroll
            for (int nf = 0; nf < 8; nf++) {
                MMA_F16(s4[nf], qfh[ks], bh[nf]);
                MMA_F16(s4[nf], qfh[ks], bl[nf]);
                MMA_F16(s4[nf], qfl[ks], bh[nf]);
            }
        }

        #pragma unroll
        for (int nf = 0; nf < 8; nf++) {
            int col = kt * 64 + nf * 8 + (lane & 3) * 2;
            bool p0 = padp[col] != 0;
            bool p1 = padp[col + 1] != 0;
            bool c0lt = col < lt, c1lt = (col + 1) < lt;
            s4[nf][0] = (p0 && (col <= rbase || c0lt))         ? s4[nf][0] : -1.0e9f;
            s4[nf][1] = (p1 && (col + 1 <= rbase || c1lt))     ? s4[nf][1] : -1.0e9f;
            s4[nf][2] = (p0 && (col <= rbase + 8 || c0lt))     ? s4[nf][2] : -1.0e9f;
            s4[nf][3] = (p1 && (col + 1 <= rbase + 8 || c1lt)) ? s4[nf][3] : -1.0e9f;
        }

        #pragma unroll
        for (int r = 0; r < 2; r++) {
            float tm = -INFINITY;
            #pragma unroll
            for (int nf = 0; nf < 8; nf++)
                tm = fmaxf(tm, fmaxf(s4[nf][2 * r], s4[nf][2 * r + 1]));
            tm = fmaxf(tm, __shfl_xor_sync(0xffffffffu, tm, 1));
            tm = fmaxf(tm, __shfl_xor_sync(0xffffffffu, tm, 2));
            float nm = fmaxf(m_[r], tm);
            float al = __expf(m_[r] - nm);
            m_[r] = nm;
            float ts = 0.0f;
            #pragma unroll
            for (int nf = 0; nf < 8; nf++) {
                float p0 = __expf(s4[nf][2 * r] - nm);
                float p1 = __expf(s4[nf][2 * r + 1] - nm);
                s4[nf][2 * r] = p0;
                s4[nf][2 * r + 1] = p1;
                ts += p0 + p1;
            }
            ts += __shfl_xor_sync(0xffffffffu, ts, 1);
            ts += __shfl_xor_sync(0xffffffffu, ts, 2);
            l_[r] = l_[r] * al + ts;
            #pragma unroll
            for (int nf = 0; nf < 8; nf++) {
                oacc[nf][2 * r] *= al;
                oacc[nf][2 * r + 1] *= al;
            }
        }

        // ---- O += P V (P split hi/lo, V single) ----
        #pragma unroll
        for (int kv = 0; kv < 4; kv++) {
            uint32_t pah[4], pal[4];
            packsplit2h(s4[2 * kv][0], s4[2 * kv][1], pah[0], pal[0]);
            packsplit2h(s4[2 * kv][2], s4[2 * kv][3], pah[1], pal[1]);
            packsplit2h(s4[2 * kv + 1][0], s4[2 * kv + 1][1], pah[2], pal[2]);
            packsplit2h(s4[2 * kv + 1][2], s4[2 * kv + 1][3], pah[3], pal[3]);
            #pragma unroll
            for (int dg = 0; dg < 4; dg++) {
                int row = kv * 16 + (lane & 7) + ((lane >> 3) & 1) * 8;
                int ch = dg * 2 + (lane >> 4);
                uint32_t so = swz(row, ch);
                uint32_t vh0, vh1, vh2, vh3;
                LDSM4T(vh0, vh1, vh2, vh3, VHs + so);
                uint32_t bfh0[2] = {vh0, vh1}, bfh1[2] = {vh2, vh3};
                MMA_F16(oacc[dg * 2], pah, bfh0);
                MMA_F16(oacc[dg * 2], pal, bfh0);
                MMA_F16(oacc[dg * 2 + 1], pah, bfh1);
                MMA_F16(oacc[dg * 2 + 1], pal, bfh1);
            }
        }

        __syncthreads();
        if (kt + 2 < 8) load_kv(kt + 2, kt & 1);
    }

    float inv0 = 1.0f / l_[0], inv1 = 1.0f / l_[1];
    const int row0 = qt * 128 + w * 16 + (lane >> 2);
    #pragma unroll
    for (int nf = 0; nf < 8; nf++) {
        int col = hh * 64 + nf * 8 + (lane & 3) * 2;
        size_t b0 = ((size_t)(b * kS + row0)) * kD + col;
        size_t b1 = ((size_t)(b * kS + row0 + 8)) * kD + col;
        uint32_t ph, pl;
        packsplit2h(oacc[nf][0] * inv0, oacc[nf][1] * inv0, ph, pl);
        *(uint32_t*)(ohi + b0) = ph;
        *(uint32_t*)(olo + b0) = pl;
        packsplit2h(oacc[nf][2] * inv1, oacc[nf][3] * inv1, ph, pl);
        *(uint32_t*)(ohi + b1) = ph;
        *(uint32_t*)(olo + b1) = pl;
    }
}

// ---------------------------------------------------------------------------
__global__ void pe_embed_kernel(const int* __restrict__ x, const int* __restrict__ tim,
                                const float* __restrict__ tok_emb,
                                const float* __restrict__ time_emb,
                                float* __restrict__ out) {
    int idx = blockIdx.x * blockDim.x + threadIdx.x;
    if (idx >= kM * kD) return;
    int bs = idx / kD;
    int j = idx - bs * kD;
    int s = bs & (kS - 1);
    int i2 = j & ~1;
    double ang = (double)s * pow(10000.0, -(double)i2 / (double)kD);
    float pe = (j & 1) ? (float)cos(ang) : (float)sin(ang);
    out[idx] = tok_emb[(size_t)x[bs] * kD + j] + time_emb[(size_t)tim[bs] * kD + j] + pe;
}

// ----------------------------- LayerNorm ------------------------------------
__device__ __forceinline__ float block_reduce_sum(float v, float* sred) {
    #pragma unroll
    for (int o = 16; o > 0; o >>= 1) v += __shfl_xor_sync(0xffffffffu, v, o);
    int w = threadIdx.x >> 5;
    __syncthreads();
    if ((threadIdx.x & 31) == 0) sred[w] = v;
    __syncthreads();
    if (threadIdx.x == 0) {
        float t = sred[0];
        #pragma unroll
        for (int i = 1; i < 8; i++) t += sred[i];
        sred[0] = t;
    }
    __syncthreads();
    return sred[0];
}

__global__ void ln_kernel(const float* __restrict__ in, float* __restrict__ out,
                          const float* __restrict__ g, const float* __restrict__ b) {
    __shared__ float sred[8];
    int row = blockIdx.x, tid = threadIdx.x;
    const float* ip = in + (size_t)row * kD;
    float v0 = ip[tid], v1 = ip[tid + 256], v2 = ip[tid + 512];
    float sum = block_reduce_sum(v0 + v1 + v2, sred);
    float mu = sum * (1.0f / 768.0f);
    float d0 = v0 - mu, d1 = v1 - mu, d2 = v2 - mu;
    float sq = block_reduce_sum(d0 * d0 + d1 * d1 + d2 * d2, sred);
    float inv = 1.0f / sqrtf(sq * (1.0f / 768.0f) + 1e-6f);
    float* op = out + (size_t)row * kD;
    op[tid]       = g[tid]       * d0 * inv + b[tid];
    op[tid + 256] = g[tid + 256] * d1 * inv + b[tid + 256];
    op[tid + 512] = g[tid + 512] * d2 * inv + b[tid + 512];
}

__global__ void ln_split_kernel(const float* __restrict__ in,
                                __half* __restrict__ ohi, __half* __restrict__ olo,
                                const float* __restrict__ g, const float* __restrict__ b) {
    __shared__ float sred[8];
    int row = blockIdx.x, tid = threadIdx.x;
    const float* ip = in + (size_t)row * kD;
    float v0 = ip[tid], v1 = ip[tid + 256], v2 = ip[tid + 512];
    float sum = block_reduce_sum(v0 + v1 + v2, sred);
    float mu = sum * (1.0f / 768.0f);
    float d0 = v0 - mu, d1 = v1 - mu, d2 = v2 - mu;
    float sq = block_reduce_sum(d0 * d0 + d1 * d1 + d2 * d2, sred);
    float inv = 1.0f / sqrtf(sq * (1.0f / 768.0f) + 1e-6f);
    size_t base = (size_t)row * kD;
    float r0 = g[tid] * d0 * inv + b[tid];
    float r1 = g[tid + 256] * d1 * inv + b[tid + 256];
    float r2 = g[tid + 512] * d2 * inv + b[tid + 512];
    __half h, l;
    hsplit(r0, h, l); ohi[base + tid]       = h; olo[base + tid]       = l;
    hsplit(r1, h, l); ohi[base + tid + 256] = h; olo[base + tid + 256] = l;
    hsplit(r2, h, l); ohi[base + tid + 512] = h; olo[base + tid + 512] = l;
}

// ---------------------------------------------------------------------------
extern "C" void kernel_launch(void* const* d_in, const int* in_sizes, int n_in,
                              void* d_out, int out_size) {
    const int*   x        = (const int*)d_in[0];
    const int*   tim      = (const int*)d_in[1];
    const int*   len_traj = (const int*)d_in[2];
    const float* tok_emb  = (const float*)d_in[3];
    const float* time_emb = (const float*)d_in[4];
    const float* emb_g    = (const float*)d_in[5];
    const float* emb_b    = (const float*)d_in[6];
    const float* Wq = (const float*)d_in[7];
    const float* bq = (const float*)d_in[8];
    const float* Wk = (const float*)d_in[9];
    const float* bk = (const float*)d_in[10];
    const float* Wv = (const float*)d_in[11];
    const float* bv = (const float*)d_in[12];
    const float* Wo = (const float*)d_in[13];
    const float* bo = (const float*)d_in[14];
    const float* ln1_g = (const float*)d_in[15];
    const float* ln1_b = (const float*)d_in[16];
    const float* W1 = (const float*)d_in[17];
    const float* b1 = (const float*)d_in[18];
    const float* W2 = (const float*)d_in[19];
    const float* b2 = (const float*)d_in[20];
    const float* ln2_g = (const float*)d_in[21];
    const float* ln2_b = (const float*)d_in[22];
    float* out = (float*)d_out;

    float *ph, *ptmp, *pbqkv;
    __half *phnh, *phnl, *pqkvh, *pqkvl, *pohi, *polo, *pffh, *pffl;
    __half *pwqkv, *pwo, *pw1, *pw2;
    cudaGetSymbolAddress((void**)&ph,    g_h);
    cudaGetSymbolAddress((void**)&ptmp,  g_tmp);
    cudaGetSymbolAddress((void**)&pbqkv, g_bqkv);
    cudaGetSymbolAddress((void**)&phnh,  g_hn_hi);
    cudaGetSymbolAddress((void**)&phnl,  g_hn_lo);
    cudaGetSymbolAddress((void**)&pqkvh, g_qkv_hi);
    cudaGetSymbolAddress((void**)&pqkvl, g_qkv_lo);
    cudaGetSymbolAddress((void**)&pohi,  g_o_hi);
    cudaGetSymbolAddress((void**)&polo,  g_o_lo);
    cudaGetSymbolAddress((void**)&pffh,  g_ff_hi);
    cudaGetSymbolAddress((void**)&pffl,  g_ff_lo);
    cudaGetSymbolAddress((void**)&pwqkv, g_wqkv);
    cudaGetSymbolAddress((void**)&pwo,   g_wo);
    cudaGetSymbolAddress((void**)&pw1,   g_w1);
    cudaGetSymbolAddress((void**)&pw2,   g_w2);

    cudaFuncSetAttribute(mma_gemm, cudaFuncAttributeMaxDynamicSharedMemorySize, kSmemBytes);
    cudaFuncSetAttribute(attn_mma, cudaFuncAttributeMaxDynamicSharedMemorySize, kAttnSmem);

    prep_w_off<<<4096, 256>>>(Wq, pwqkv, kD, kD, kQKV, 0, 0.125f);
    prep_w_off<<<4096, 256>>>(Wk, pwqkv, kD, kD, kQKV, 6, 1.0f);
    prep_w_off<<<4096, 256>>>(Wv, pwqkv, kD, kD, kQKV, 12, 1.0f);
    prep_w_off<<<4096, 256>>>(Wo, pwo, kD, kD, kD, 0, 1.0f);
    prep_w_off<<<8192, 256>>>(W1, pw1, kD, kFF, kFF, 0, 1.0f);
    prep_w_off<<<8192, 256>>>(W2, pw2, kFF, kD, kD, 0, 1.0f);
    bias_qkv_kernel<<<(kL * kQKV + 255) / 256, 256>>>(bq, bk, bv, pbqkv);

    pe_embed_kernel<<<(kM * kD + 255) / 256, 256>>>(x, tim, tok_emb, time_emb, ptmp);
    ln_kernel<<<kM, 256>>>(ptmp, ph, emb_g, emb_b);

    const dim3 gQKV(kQKV / 128, kM / 128);   // 18 x 128
    const dim3 gProj(kD / 128, kM / 128);    // 6 x 128
    const dim3 gFF1(kFF / 128, kM / 128);    // 24 x 128
    const dim3 gAttn(kS / 128, kH, kB);

    for (int i = 0; i < kL; i++) {
        const size_t wQ = (size_t)i * kD * kQKV;
        const size_t wD = (size_t)i * kD * kD;
        const size_t wF = (size_t)i * kD * kFF;
        ln_split_kernel<<<kM, 256>>>(ph, phnh, phnl, ln1_g + i * kD, ln1_b + i * kD);
        mma_gemm<<<gQKV, 256, kSmemBytes>>>(phnh, phnl, pwqkv + wQ, pbqkv + i * kQKV,
                                            nullptr, nullptr, pqkvh, pqkvl, kQKV, kD, 3);
        attn_mma<<<gAttn, 256, kAttnSmem>>>(pqkvh, pqkvl, pqkvh + kD, pqkvl + kD,
                                            pqkvh + 2 * kD, kQKV, x, len_traj, pohi, polo);
        mma_gemm<<<gProj, 256, kSmemBytes>>>(pohi, polo, pwo + wD, bo + i * kD,
                                             ph, ph, nullptr, nullptr, kD, kD, 1);
        ln_split_kernel<<<kM, 256>>>(ph, phnh, phnl, ln2_g + i * kD, ln2_b + i * kD);
        mma_gemm<<<gFF1, 256, kSmemBytes>>>(phnh, phnl, pw1 + wF, b1 + i * kFF,
                                            nullptr, nullptr, pffh, pffl, kFF, kD, 2);
        float* cdst = (i == kL - 1) ? out : ph;
        mma_gemm<<<gProj, 256, kSmemBytes>>>(pffh, pffl, pw2 + wF, b2 + i * kD,
                                             ph, cdst, nullptr, nullptr, kD, kFF, 1);
    }
}

// round 7
// speedup vs baseline: 5.2515x; 1.4207x over previous
#include <cuda_runtime.h>
#include <cuda_fp16.h>
#include <math.h>
#include <stdint.h>

// ---------------------------------------------------------------------------
// Bert_Traj_Model: B=32, S=512, D=768, H=12, dh=64, FF=3072, L=12, fp32 I/O.
// Round 6: single-product fp16 GEMMs (A fp16 x W fp16, fp32 accum), 4-stage
// cp.async pipeline with ONE barrier per iteration. Attention: QK 3-product
// (q,k hi/lo), PV 2-product. Q-scale folded into Wq at prep.
// ---------------------------------------------------------------------------

namespace {
constexpr int kB  = 32;
constexpr int kS  = 512;
constexpr int kD  = 768;
constexpr int kH  = 12;
constexpr int kFF = 3072;
constexpr int kL  = 12;
constexpr int kM  = kB * kS;               // 16384 rows
constexpr int kQKV = 3 * kD;               // 2304
constexpr int kStageBytes = 16384;         // A 8K, B 8K
constexpr int kNS = 4;
constexpr int kSmemBytes = kNS * kStageBytes;       // 64KB
constexpr int kAttnSmem = 32768 + 2 * 24576 + 512;  // 82432
}

// ----------------------------- scratch (no allocs allowed) ------------------
__device__ float g_h  [(size_t)kM * kD];
__device__ float g_tmp[(size_t)kM * kD];
__device__ float g_bqkv[kL * kQKV];
__device__ __half g_hn    [(size_t)kM * kD];
__device__ __half g_qkv_hi[(size_t)kM * kQKV];
__device__ __half g_qkv_lo[(size_t)kM * kQKV];
__device__ __half g_o     [(size_t)kM * kD];
__device__ __half g_ff    [(size_t)kM * kFF];
// pre-tiled fp16 weights: blocks of 128(n) x 32(k), row-major in block
__device__ __half g_wqkv[(size_t)kL * kD * kQKV];
__device__ __half g_wo  [(size_t)kL * kD * kD];
__device__ __half g_w1  [(size_t)kL * kD * kFF];
__device__ __half g_w2  [(size_t)kL * kFF * kD];

// ----------------------------- PTX helpers ---------------------------------
__device__ __forceinline__ uint32_t smem_u32(const void* p) {
    uint32_t a;
    asm("{ .reg .u64 t; cvta.to.shared.u64 t, %1; cvt.u32.u64 %0, t; }" : "=r"(a) : "l"(p));
    return a;
}
#define CP16(dst, src) asm volatile("cp.async.cg.shared.global [%0], [%1], 16;" :: "r"(dst), "l"(src))
#define CP_COMMIT()    asm volatile("cp.async.commit_group;" ::: "memory")
#define CP_WAIT(n)     asm volatile("cp.async.wait_group %0;" :: "n"(n) : "memory")

#define LDSM4(r0, r1, r2, r3, a)                                                \
    asm volatile("ldmatrix.sync.aligned.m8n8.x4.shared.b16 {%0,%1,%2,%3}, [%4];" \
                 : "=r"(r0), "=r"(r1), "=r"(r2), "=r"(r3) : "r"(a))
#define LDSM4T(r0, r1, r2, r3, a)                                               \
    asm volatile("ldmatrix.sync.aligned.m8n8.x4.trans.shared.b16 {%0,%1,%2,%3}, [%4];" \
                 : "=r"(r0), "=r"(r1), "=r"(r2), "=r"(r3) : "r"(a))
#define MMA_F16(d, a, b)                                                        \
    asm volatile("mma.sync.aligned.m16n8k16.row.col.f32.f16.f16.f32 "           \
                 "{%0,%1,%2,%3}, {%4,%5,%6,%7}, {%8,%9}, {%0,%1,%2,%3};"        \
                 : "+f"((d)[0]), "+f"((d)[1]), "+f"((d)[2]), "+f"((d)[3])       \
                 : "r"((a)[0]), "r"((a)[1]), "r"((a)[2]), "r"((a)[3]),          \
                   "r"((b)[0]), "r"((b)[1]))

__device__ __forceinline__ void packsplit2h(float a, float b, uint32_t& ph, uint32_t& pl) {
    __half ha = __float2half_rn(a), hb = __float2half_rn(b);
    __half la = __float2half_rn(a - __half2float(ha));
    __half lb = __float2half_rn(b - __half2float(hb));
    __half2 th = __halves2half2(ha, hb), tl = __halves2half2(la, lb);
    ph = *(uint32_t*)&th;
    pl = *(uint32_t*)&tl;
}
__device__ __forceinline__ uint32_t soff(int row, int ch) {   // 64B rows
    return (uint32_t)(row * 64 + ((ch ^ ((row >> 1) & 3)) << 4));
}
__device__ __forceinline__ uint32_t swz(int row, int ch) {    // 128B rows
    return (uint32_t)(row * 128 + ((ch ^ (row & 7)) << 4));
}

// ---------------------------------------------------------------------------
// Weight prep: W[L][K][Nsrc] fp32 -> fp16 tiles of 128n x 32k at nt offset.
// ---------------------------------------------------------------------------
__global__ void prep_w_off(const float* __restrict__ W, __half* __restrict__ dst,
                           int K, int Nsrc, int Ntot, int ntoff, float scale) {
    size_t total = (size_t)kL * K * Nsrc;
    int kcnt = K / 32;
    size_t per_dst = (size_t)K * Ntot;
    for (size_t idx = (size_t)blockIdx.x * blockDim.x + threadIdx.x; idx < total;
         idx += (size_t)gridDim.x * blockDim.x) {
        size_t per = (size_t)K * Nsrc;
        int l = (int)(idx / per);
        int rem = (int)(idx - (size_t)l * per);
        int k = rem / Nsrc, n = rem - k * Nsrc;
        float v = W[idx] * scale;
        int ntg = ntoff + (n >> 7);
        size_t d = (size_t)l * per_dst + ((size_t)(ntg * kcnt + (k >> 5))) * 4096
                 + (n & 127) * 32 + (k & 31);
        dst[d] = __float2half_rn(v);
    }
}

__global__ void bias_qkv_kernel(const float* __restrict__ bq, const float* __restrict__ bk,
                                const float* __restrict__ bv, float* __restrict__ dst) {
    int idx = blockIdx.x * blockDim.x + threadIdx.x;
    if (idx >= kL * kQKV) return;
    int l = idx / kQKV, j = idx - l * kQKV;
    float v;
    if (j < kD)            v = 0.125f * bq[l * kD + j];
    else if (j < 2 * kD)   v = bk[l * kD + j - kD];
    else                   v = bv[l * kD + j - 2 * kD];
    dst[idx] = v;
}

// ---------------------------------------------------------------------------
// mma_gemm: C[M,N] = epi(A @ W + bias). A single fp16, W fp16 tiles.
// modes: 1=+Res fp32 out, 2=relu fp16 out, 3=fp16 hi/lo split out (QKV).
// 128x128 CTA tile, 8 warps of 32x64, 4-stage cp.async, 1 barrier/iter.
// ---------------------------------------------------------------------------
__global__ void __launch_bounds__(256, 2)
mma_gemm(const __half* __restrict__ Ah, const __half* __restrict__ Bw,
         const float* __restrict__ bias, const float* __restrict__ Res,
         float* __restrict__ C, __half* __restrict__ Chi, __half* __restrict__ Clo,
         int N, int K, int mode) {
    extern __shared__ char smem[];
    const uint32_t sb = smem_u32(smem);
    const int tid = threadIdx.x;
    const int lane = tid & 31, wid = tid >> 5;
    const int wm = (wid & 3) * 32, wn = (wid >> 2) * 64;
    const int m0 = blockIdx.y * 128, n0 = blockIdx.x * 128;
    const int iters = K >> 5;
    const size_t btile = (size_t)blockIdx.x * iters * 4096;

    float acc[2][8][4];
    #pragma unroll
    for (int a = 0; a < 2; a++)
        #pragma unroll
        for (int b = 0; b < 8; b++)
            #pragma unroll
            for (int c = 0; c < 4; c++) acc[a][b][c] = 0.0f;

    auto load_stage = [&](int c, int s) {
        const uint32_t st = sb + (uint32_t)s * kStageBytes;
        #pragma unroll
        for (int p = 0; p < 2; p++) {
            int idx = p * 256 + tid;
            int row = idx >> 2, ch = idx & 3;
            uint32_t so = soff(row, ch);
            const __half* gA = Ah + (size_t)(m0 + row) * K + c * 32 + ch * 8;
            size_t boff = btile + (size_t)c * 4096 + row * 32 + ch * 8;
            CP16(st + so, gA);
            CP16(st + 8192 + so, Bw + boff);
        }
        CP_COMMIT();
    };

    auto compute_stage = [&](int s) {
        const uint32_t base = sb + (uint32_t)s * kStageBytes;
        #pragma unroll
        for (int ks = 0; ks < 2; ks++) {
            const int kc = ks * 2;
            uint32_t ah[2][4], bh[8][2];
            #pragma unroll
            for (int mf = 0; mf < 2; mf++) {
                int row = wm + mf * 16 + (lane & 15);
                int ch = kc + (lane >> 4);
                LDSM4(ah[mf][0], ah[mf][1], ah[mf][2], ah[mf][3], base + soff(row, ch));
            }
            #pragma unroll
            for (int nb = 0; nb < 4; nb++) {
                int row = wn + nb * 16 + (lane & 7) + ((lane >> 4) << 3);
                int ch = kc + ((lane >> 3) & 1);
                LDSM4(bh[2 * nb][0], bh[2 * nb][1], bh[2 * nb + 1][0], bh[2 * nb + 1][1],
                      base + 8192 + soff(row, ch));
            }
            #pragma unroll
            for (int mf = 0; mf < 2; mf++)
                #pragma unroll
                for (int nf = 0; nf < 8; nf++)
                    MMA_F16(acc[mf][nf], ah[mf], bh[nf]);
        }
    };

    load_stage(0, 0);
    load_stage(1, 1);
    load_stage(2, 2);

    for (int c = 0; c < iters; c++) {
        const int rem = iters - 1 - c;
        if (rem >= 2) CP_WAIT(2);
        else if (rem == 1) CP_WAIT(1);
        else CP_WAIT(0);
        __syncthreads();
        if (c + 3 < iters) load_stage(c + 3, (c + 3) & 3);
        compute_stage(c & 3);
    }

    #pragma unroll
    for (int mf = 0; mf < 2; mf++) {
        #pragma unroll
        for (int h = 0; h < 2; h++) {
            const int r = m0 + wm + mf * 16 + (lane >> 2) + h * 8;
            #pragma unroll
            for (int nf = 0; nf < 8; nf++) {
                const int cc = n0 + wn + nf * 8 + (lane & 3) * 2;
                float v0 = acc[mf][nf][h * 2 + 0] + bias[cc];
                float v1 = acc[mf][nf][h * 2 + 1] + bias[cc + 1];
                size_t base = (size_t)r * N + cc;
                if (mode == 3) {
                    uint32_t ph, pl;
                    packsplit2h(v0, v1, ph, pl);
                    *(uint32_t*)(Chi + base) = ph;
                    *(uint32_t*)(Clo + base) = pl;
                } else if (mode == 2) {
                    v0 = fmaxf(v0, 0.0f);
                    v1 = fmaxf(v1, 0.0f);
                    __half2 t = __halves2half2(__float2half_rn(v0), __float2half_rn(v1));
                    *(uint32_t*)(Chi + base) = *(uint32_t*)&t;
                } else {
                    float2 rr = *(const float2*)(Res + base);
                    float2 o;
                    o.x = v0 + rr.x;
                    o.y = v1 + rr.y;
                    *(float2*)(C + base) = o;
                }
            }
        }
    }
}

// ---------------------------------------------------------------------------
// attn_mma: flash attention. QK 3-product (q,k split), PV 2-product (P split,
// V single). Output single fp16. Block: 128 q-rows x (head, batch).
// smem: Qh 16K | Ql 16K | 2 stages x (Kh 8K|Kl 8K|Vh 8K) | pad 512
// ---------------------------------------------------------------------------
__global__ void __launch_bounds__(256, 1)
attn_mma(const __half* __restrict__ qh_g, const __half* __restrict__ ql_g,
         const __half* __restrict__ kh_g, const __half* __restrict__ kl_g,
         const __half* __restrict__ vh_g, int rstride,
         const int* __restrict__ xtok, const int* __restrict__ ltp,
         __half* __restrict__ oh_g) {
    extern __shared__ char smem[];
    const uint32_t sb = smem_u32(smem);
    const int tid = threadIdx.x, lane = tid & 31, w = tid >> 5;
    const int qt = blockIdx.x, hh = blockIdx.y, b = blockIdx.z;
    const int lt = ltp[0];

    const uint32_t QH = sb, QL = sb + 16384;
    const uint32_t STG = sb + 32768;      // + s*24576: Kh, Kl, Vh (8K each)
    char* padp = smem + 32768 + 2 * 24576;

    #pragma unroll
    for (int i = 0; i < 2; i++)
        padp[tid + i * 256] = (xtok[b * kS + tid + i * 256] > 0) ? 1 : 0;

    const size_t qgbase = ((size_t)(b * kS + qt * 128)) * rstride + hh * 64;
    #pragma unroll
    for (int i = 0; i < 4; i++) {
        int idx = i * 256 + tid;
        int row = idx >> 3, ch = idx & 7;
        uint32_t so = swz(row, ch);
        size_t go = qgbase + (size_t)row * rstride + ch * 8;
        CP16(QH + so, qh_g + go);
        CP16(QL + so, ql_g + go);
    }
    CP_COMMIT();

    auto load_kv = [&](int kt, int s) {
        const uint32_t st = STG + (uint32_t)s * 24576;
        const size_t gb = ((size_t)(b * kS + kt * 64)) * rstride + hh * 64;
        #pragma unroll
        for (int i = 0; i < 2; i++) {
            int idx = i * 256 + tid;
            int row = idx >> 3, ch = idx & 7;
            uint32_t so = swz(row, ch);
            size_t go = gb + (size_t)row * rstride + ch * 8;
            CP16(st + so,         kh_g + go);
            CP16(st + 8192 + so,  kl_g + go);
            CP16(st + 16384 + so, vh_g + go);
        }
        CP_COMMIT();
    };

    load_kv(0, 0);
    load_kv(1, 1);

    uint32_t qfh[4][4], qfl[4][4];
    float oacc[8][4];
    #pragma unroll
    for (int i = 0; i < 8; i++)
        #pragma unroll
        for (int j = 0; j < 4; j++) oacc[i][j] = 0.0f;
    float m_[2] = {-INFINITY, -INFINITY}, l_[2] = {0.0f, 0.0f};

    const int rbase = qt * 128 + w * 16 + (lane >> 2);

    for (int kt = 0; kt < 8; kt++) {
        if (kt < 7) { CP_WAIT(1); } else { CP_WAIT(0); }
        __syncthreads();

        if (kt == 0) {
            #pragma unroll
            for (int ks = 0; ks < 4; ks++) {
                int row = w * 16 + (lane & 15);
                int ch = ks * 2 + (lane >> 4);
                uint32_t so = swz(row, ch);
                LDSM4(qfh[ks][0], qfh[ks][1], qfh[ks][2], qfh[ks][3], QH + so);
                LDSM4(qfl[ks][0], qfl[ks][1], qfl[ks][2], qfl[ks][3], QL + so);
            }
        }

        const uint32_t st = STG + (uint32_t)(kt & 1) * 24576;
        const uint32_t KHs = st, KLs = st + 8192, VHs = st + 16384;

        float s4[8][4];
        #pragma unroll
        for (int i = 0; i < 8; i++)
            #pragma unroll
            for (int j = 0; j < 4; j++) s4[i][j] = 0.0f;

        #pragma unroll
        for (int ks = 0; ks < 4; ks++) {
            uint32_t bh[8][2], bl[8][2];
            #pragma unroll
            for (int kg = 0; kg < 4; kg++) {
                int row = kg * 16 + (lane & 7) + ((lane >> 4) << 3);
                int ch = ks * 2 + ((lane >> 3) & 1);
                uint32_t so = swz(row, ch);
                LDSM4(bh[2 * kg][0], bh[2 * kg][1], bh[2 * kg + 1][0], bh[2 * kg + 1][1],
                      KHs + so);
                LDSM4(bl[2 * kg][0], bl[2 * kg][1], bl[2 * kg + 1][0], bl[2 * kg + 1][1],
                      KLs + so);
            }
            #pragma unroll
            for (int nf = 0; nf < 8; nf++) {
                MMA_F16(s4[nf], qfh[ks], bh[nf]);
                MMA_F16(s4[nf], qfh[ks], bl[nf]);
                MMA_F16(s4[nf], qfl[ks], bh[nf]);
            }
        }

        #pragma unroll
        for (int nf = 0; nf < 8; nf++) {
            int col = kt * 64 + nf * 8 + (lane & 3) * 2;
            bool p0 = padp[col] != 0;
            bool p1 = padp[col + 1] != 0;
            bool c0lt = col < lt, c1lt = (col + 1) < lt;
            s4[nf][0] = (p0 && (col <= rbase || c0lt))         ? s4[nf][0] : -1.0e9f;
            s4[nf][1] = (p1 && (col + 1 <= rbase || c1lt))     ? s4[nf][1] : -1.0e9f;
            s4[nf][2] = (p0 && (col <= rbase + 8 || c0lt))     ? s4[nf][2] : -1.0e9f;
            s4[nf][3] = (p1 && (col + 1 <= rbase + 8 || c1lt)) ? s4[nf][3] : -1.0e9f;
        }

        #pragma unroll
        for (int r = 0; r < 2; r++) {
            float tm = -INFINITY;
            #pragma unroll
            for (int nf = 0; nf < 8; nf++)
                tm = fmaxf(tm, fmaxf(s4[nf][2 * r], s4[nf][2 * r + 1]));
            tm = fmaxf(tm, __shfl_xor_sync(0xffffffffu, tm, 1));
            tm = fmaxf(tm, __shfl_xor_sync(0xffffffffu, tm, 2));
            float nm = fmaxf(m_[r], tm);
            float al = __expf(m_[r] - nm);
            m_[r] = nm;
            float ts = 0.0f;
            #pragma unroll
            for (int nf = 0; nf < 8; nf++) {
                float p0 = __expf(s4[nf][2 * r] - nm);
                float p1 = __expf(s4[nf][2 * r + 1] - nm);
                s4[nf][2 * r] = p0;
                s4[nf][2 * r + 1] = p1;
                ts += p0 + p1;
            }
            ts += __shfl_xor_sync(0xffffffffu, ts, 1);
            ts += __shfl_xor_sync(0xffffffffu, ts, 2);
            l_[r] = l_[r] * al + ts;
            #pragma unroll
            for (int nf = 0; nf < 8; nf++) {
                oacc[nf][2 * r] *= al;
                oacc[nf][2 * r + 1] *= al;
            }
        }

        // ---- O += P V (P split hi/lo, V single) ----
        #pragma unroll
        for (int kv = 0; kv < 4; kv++) {
            uint32_t pah[4], pal[4];
            packsplit2h(s4[2 * kv][0], s4[2 * kv][1], pah[0], pal[0]);
            packsplit2h(s4[2 * kv][2], s4[2 * kv][3], pah[1], pal[1]);
            packsplit2h(s4[2 * kv + 1][0], s4[2 * kv + 1][1], pah[2], pal[2]);
            packsplit2h(s4[2 * kv + 1][2], s4[2 * kv + 1][3], pah[3], pal[3]);
            #pragma unroll
            for (int dg = 0; dg < 4; dg++) {
                int row = kv * 16 + (lane & 7) + ((lane >> 3) & 1) * 8;
                int ch = dg * 2 + (lane >> 4);
                uint32_t so = swz(row, ch);
                uint32_t vh0, vh1, vh2, vh3;
                LDSM4T(vh0, vh1, vh2, vh3, VHs + so);
                uint32_t bfh0[2] = {vh0, vh1}, bfh1[2] = {vh2, vh3};
                MMA_F16(oacc[dg * 2], pah, bfh0);
                MMA_F16(oacc[dg * 2], pal, bfh0);
                MMA_F16(oacc[dg * 2 + 1], pah, bfh1);
                MMA_F16(oacc[dg * 2 + 1], pal, bfh1);
            }
        }

        __syncthreads();
        if (kt + 2 < 8) load_kv(kt + 2, kt & 1);
    }

    float inv0 = 1.0f / l_[0], inv1 = 1.0f / l_[1];
    const int row0 = qt * 128 + w * 16 + (lane >> 2);
    #pragma unroll
    for (int nf = 0; nf < 8; nf++) {
        int col = hh * 64 + nf * 8 + (lane & 3) * 2;
        size_t b0 = ((size_t)(b * kS + row0)) * kD + col;
        size_t b1 = ((size_t)(b * kS + row0 + 8)) * kD + col;
        __half2 t0 = __halves2half2(__float2half_rn(oacc[nf][0] * inv0),
                                    __float2half_rn(oacc[nf][1] * inv0));
        __half2 t1 = __halves2half2(__float2half_rn(oacc[nf][2] * inv1),
                                    __float2half_rn(oacc[nf][3] * inv1));
        *(uint32_t*)(oh_g + b0) = *(uint32_t*)&t0;
        *(uint32_t*)(oh_g + b1) = *(uint32_t*)&t1;
    }
}

// ---------------------------------------------------------------------------
__global__ void pe_embed_kernel(const int* __restrict__ x, const int* __restrict__ tim,
                                const float* __restrict__ tok_emb,
                                const float* __restrict__ time_emb,
                                float* __restrict__ out) {
    int idx = blockIdx.x * blockDim.x + threadIdx.x;
    if (idx >= kM * kD) return;
    int bs = idx / kD;
    int j = idx - bs * kD;
    int s = bs & (kS - 1);
    int i2 = j & ~1;
    double ang = (double)s * pow(10000.0, -(double)i2 / (double)kD);
    float pe = (j & 1) ? (float)cos(ang) : (float)sin(ang);
    out[idx] = tok_emb[(size_t)x[bs] * kD + j] + time_emb[(size_t)tim[bs] * kD + j] + pe;
}

// ----------------------------- LayerNorm ------------------------------------
__device__ __forceinline__ float block_reduce_sum(float v, float* sred) {
    #pragma unroll
    for (int o = 16; o > 0; o >>= 1) v += __shfl_xor_sync(0xffffffffu, v, o);
    int w = threadIdx.x >> 5;
    __syncthreads();
    if ((threadIdx.x & 31) == 0) sred[w] = v;
    __syncthreads();
    if (threadIdx.x == 0) {
        float t = sred[0];
        #pragma unroll
        for (int i = 1; i < 8; i++) t += sred[i];
        sred[0] = t;
    }
    __syncthreads();
    return sred[0];
}

__global__ void ln_kernel(const float* __restrict__ in, float* __restrict__ out,
                          const float* __restrict__ g, const float* __restrict__ b) {
    __shared__ float sred[8];
    int row = blockIdx.x, tid = threadIdx.x;
    const float* ip = in + (size_t)row * kD;
    float v0 = ip[tid], v1 = ip[tid + 256], v2 = ip[tid + 512];
    float sum = block_reduce_sum(v0 + v1 + v2, sred);
    float mu = sum * (1.0f / 768.0f);
    float d0 = v0 - mu, d1 = v1 - mu, d2 = v2 - mu;
    float sq = block_reduce_sum(d0 * d0 + d1 * d1 + d2 * d2, sred);
    float inv = 1.0f / sqrtf(sq * (1.0f / 768.0f) + 1e-6f);
    float* op = out + (size_t)row * kD;
    op[tid]       = g[tid]       * d0 * inv + b[tid];
    op[tid + 256] = g[tid + 256] * d1 * inv + b[tid + 256];
    op[tid + 512] = g[tid + 512] * d2 * inv + b[tid + 512];
}

__global__ void ln_h16_kernel(const float* __restrict__ in, __half* __restrict__ out,
                              const float* __restrict__ g, const float* __restrict__ b) {
    __shared__ float sred[8];
    int row = blockIdx.x, tid = threadIdx.x;
    const float* ip = in + (size_t)row * kD;
    float v0 = ip[tid], v1 = ip[tid + 256], v2 = ip[tid + 512];
    float sum = block_reduce_sum(v0 + v1 + v2, sred);
    float mu = sum * (1.0f / 768.0f);
    float d0 = v0 - mu, d1 = v1 - mu, d2 = v2 - mu;
    float sq = block_reduce_sum(d0 * d0 + d1 * d1 + d2 * d2, sred);
    float inv = 1.0f / sqrtf(sq * (1.0f / 768.0f) + 1e-6f);
    size_t base = (size_t)row * kD;
    out[base + tid]       = __float2half_rn(g[tid]       * d0 * inv + b[tid]);
    out[base + tid + 256] = __float2half_rn(g[tid + 256] * d1 * inv + b[tid + 256]);
    out[base + tid + 512] = __float2half_rn(g[tid + 512] * d2 * inv + b[tid + 512]);
}

// ---------------------------------------------------------------------------
extern "C" void kernel_launch(void* const* d_in, const int* in_sizes, int n_in,
                              void* d_out, int out_size) {
    const int*   x        = (const int*)d_in[0];
    const int*   tim      = (const int*)d_in[1];
    const int*   len_traj = (const int*)d_in[2];
    const float* tok_emb  = (const float*)d_in[3];
    const float* time_emb = (const float*)d_in[4];
    const float* emb_g    = (const float*)d_in[5];
    const float* emb_b    = (const float*)d_in[6];
    const float* Wq = (const float*)d_in[7];
    const float* bq = (const float*)d_in[8];
    const float* Wk = (const float*)d_in[9];
    const float* bk = (const float*)d_in[10];
    const float* Wv = (const float*)d_in[11];
    const float* bv = (const float*)d_in[12];
    const float* Wo = (const float*)d_in[13];
    const float* bo = (const float*)d_in[14];
    const float* ln1_g = (const float*)d_in[15];
    const float* ln1_b = (const float*)d_in[16];
    const float* W1 = (const float*)d_in[17];
    const float* b1 = (const float*)d_in[18];
    const float* W2 = (const float*)d_in[19];
    const float* b2 = (const float*)d_in[20];
    const float* ln2_g = (const float*)d_in[21];
    const float* ln2_b = (const float*)d_in[22];
    float* out = (float*)d_out;

    float *ph, *ptmp, *pbqkv;
    __half *phn, *pqkvh, *pqkvl, *po, *pff;
    __half *pwqkv, *pwo, *pw1, *pw2;
    cudaGetSymbolAddress((void**)&ph,    g_h);
    cudaGetSymbolAddress((void**)&ptmp,  g_tmp);
    cudaGetSymbolAddress((void**)&pbqkv, g_bqkv);
    cudaGetSymbolAddress((void**)&phn,   g_hn);
    cudaGetSymbolAddress((void**)&pqkvh, g_qkv_hi);
    cudaGetSymbolAddress((void**)&pqkvl, g_qkv_lo);
    cudaGetSymbolAddress((void**)&po,    g_o);
    cudaGetSymbolAddress((void**)&pff,   g_ff);
    cudaGetSymbolAddress((void**)&pwqkv, g_wqkv);
    cudaGetSymbolAddress((void**)&pwo,   g_wo);
    cudaGetSymbolAddress((void**)&pw1,   g_w1);
    cudaGetSymbolAddress((void**)&pw2,   g_w2);

    cudaFuncSetAttribute(mma_gemm, cudaFuncAttributeMaxDynamicSharedMemorySize, kSmemBytes);
    cudaFuncSetAttribute(attn_mma, cudaFuncAttributeMaxDynamicSharedMemorySize, kAttnSmem);

    prep_w_off<<<4096, 256>>>(Wq, pwqkv, kD, kD, kQKV, 0, 0.125f);
    prep_w_off<<<4096, 256>>>(Wk, pwqkv, kD, kD, kQKV, 6, 1.0f);
    prep_w_off<<<4096, 256>>>(Wv, pwqkv, kD, kD, kQKV, 12, 1.0f);
    prep_w_off<<<4096, 256>>>(Wo, pwo, kD, kD, kD, 0, 1.0f);
    prep_w_off<<<8192, 256>>>(W1, pw1, kD, kFF, kFF, 0, 1.0f);
    prep_w_off<<<8192, 256>>>(W2, pw2, kFF, kD, kD, 0, 1.0f);
    bias_qkv_kernel<<<(kL * kQKV + 255) / 256, 256>>>(bq, bk, bv, pbqkv);

    pe_embed_kernel<<<(kM * kD + 255) / 256, 256>>>(x, tim, tok_emb, time_emb, ptmp);
    ln_kernel<<<kM, 256>>>(ptmp, ph, emb_g, emb_b);

    const dim3 gQKV(kQKV / 128, kM / 128);   // 18 x 128
    const dim3 gProj(kD / 128, kM / 128);    // 6 x 128
    const dim3 gFF1(kFF / 128, kM / 128);    // 24 x 128
    const dim3 gAttn(kS / 128, kH, kB);

    for (int i = 0; i < kL; i++) {
        const size_t wQ = (size_t)i * kD * kQKV;
        const size_t wD = (size_t)i * kD * kD;
        const size_t wF = (size_t)i * kD * kFF;
        ln_h16_kernel<<<kM, 256>>>(ph, phn, ln1_g + i * kD, ln1_b + i * kD);
        mma_gemm<<<gQKV, 256, kSmemBytes>>>(phn, pwqkv + wQ, pbqkv + i * kQKV,
                                            nullptr, nullptr, pqkvh, pqkvl, kQKV, kD, 3);
        attn_mma<<<gAttn, 256, kAttnSmem>>>(pqkvh, pqkvl, pqkvh + kD, pqkvl + kD,
                                            pqkvh + 2 * kD, kQKV, x, len_traj, po);
        mma_gemm<<<gProj, 256, kSmemBytes>>>(po, pwo + wD, bo + i * kD,
                                             ph, ph, nullptr, nullptr, kD, kD, 1);
        ln_h16_kernel<<<kM, 256>>>(ph, phn, ln2_g + i * kD, ln2_b + i * kD);
        mma_gemm<<<gFF1, 256, kSmemBytes>>>(phn, pw1 + wF, b1 + i * kFF,
                                            nullptr, nullptr, pff, nullptr, kFF, kD, 2);
        float* cdst = (i == kL - 1) ? out : ph;
        mma_gemm<<<gProj, 256, kSmemBytes>>>(pff, pw2 + wF, b2 + i * kD,
                                             ph, cdst, nullptr, nullptr, kD, kFF, 1);
    }
}